// round 2
// baseline (speedup 1.0000x reference)
#include <cuda_runtime.h>
#include <cstdint>

// Problem constants
#define BATCH 4
#define SEQ   2048
#define EMBD  1024
#define NHEAD 16
#define HDIM  64
#define BT    (BATCH*SEQ)        // 8192
#define C3    (3*EMBD)           // 3072

// Scratch (device globals — no allocation allowed)
__device__ float g_qkv[(size_t)BT * C3];   // [bt, 3C] interleaved q|k|v
__device__ float g_y[(size_t)BT * EMBD];   // attention output [b,t,c]

// ---------------------------------------------------------------------------
// SGEMM 128x128x8, 256 threads, 8x8 per-thread tile, bias epilogue.
// C[M,N] = A[M,K] @ B[K,N] + bias[N]
// ---------------------------------------------------------------------------
__global__ __launch_bounds__(256) void sgemm_bias(
    const float* __restrict__ A, const float* __restrict__ B,
    const float* __restrict__ bias, float* __restrict__ Cout,
    int M, int N, int K)
{
    __shared__ __align__(16) float As[8][128];
    __shared__ __align__(16) float Bs[8][128];

    const int tid = threadIdx.x;
    const int tx = tid & 15;          // 0..15 -> N direction
    const int ty = tid >> 4;          // 0..15 -> M direction
    const int row0 = blockIdx.y * 128;
    const int col0 = blockIdx.x * 128;

    // A tile load mapping: 128 rows x 8 k -> 256 float4 (one per thread)
    const int a_row = tid >> 1;
    const int a_k   = (tid & 1) * 4;
    // B tile load mapping: 8 k x 128 cols -> 256 float4
    const int b_k   = tid >> 5;
    const int b_col = (tid & 31) * 4;

    const float* Aptr = A + (size_t)(row0 + a_row) * K + a_k;
    const float* Bptr = B + (size_t)b_k * N + col0 + b_col;

    float acc[8][8];
    #pragma unroll
    for (int i = 0; i < 8; i++)
        #pragma unroll
        for (int j = 0; j < 8; j++) acc[i][j] = 0.0f;

    for (int k0 = 0; k0 < K; k0 += 8) {
        float4 av = *(const float4*)Aptr;  Aptr += 8;
        float4 bv = *(const float4*)Bptr;  Bptr += (size_t)8 * N;

        As[a_k + 0][a_row] = av.x;
        As[a_k + 1][a_row] = av.y;
        As[a_k + 2][a_row] = av.z;
        As[a_k + 3][a_row] = av.w;
        *(float4*)&Bs[b_k][b_col] = bv;
        __syncthreads();

        #pragma unroll
        for (int kk = 0; kk < 8; kk++) {
            float4 a0 = *(const float4*)&As[kk][ty * 8];
            float4 a1 = *(const float4*)&As[kk][ty * 8 + 4];
            float4 b0 = *(const float4*)&Bs[kk][tx * 8];
            float4 b1 = *(const float4*)&Bs[kk][tx * 8 + 4];
            float af[8] = {a0.x,a0.y,a0.z,a0.w,a1.x,a1.y,a1.z,a1.w};
            float bf[8] = {b0.x,b0.y,b0.z,b0.w,b1.x,b1.y,b1.z,b1.w};
            #pragma unroll
            for (int i = 0; i < 8; i++)
                #pragma unroll
                for (int j = 0; j < 8; j++)
                    acc[i][j] = fmaf(af[i], bf[j], acc[i][j]);
        }
        __syncthreads();
    }

    #pragma unroll
    for (int i = 0; i < 8; i++) {
        const int r = row0 + ty * 8 + i;
        #pragma unroll
        for (int j = 0; j < 8; j += 4) {
            const int c = col0 + tx * 8 + j;
            float4 o;
            o.x = acc[i][j + 0] + bias[c + 0];
            o.y = acc[i][j + 1] + bias[c + 1];
            o.z = acc[i][j + 2] + bias[c + 2];
            o.w = acc[i][j + 3] + bias[c + 3];
            *(float4*)(Cout + (size_t)r * N + c) = o;
        }
    }
}

// ---------------------------------------------------------------------------
// Flash attention (causal), fp32.
// Block: BQ=128 queries of one (b,h). Streams BKV=64 key tiles.
// Thread layout 16x16: each thread owns 8 query rows x 4 key cols of S,
// and 8 rows x 4 d-cols of O. Row softmax reductions via shfl over 16 lanes.
// ---------------------------------------------------------------------------
#define BQ  128
#define BKV 64
#define QS_LD  132   // [HDIM][BQ+4]
#define KS_LD  68    // [HDIM][BKV+4]
#define VS_LD  68    // [BKV][HDIM+4]
#define PS_LD  68    // [BQ][BKV+4]
#define ATTN_SMEM_FLOATS (HDIM*QS_LD + HDIM*KS_LD + BKV*VS_LD + BQ*PS_LD)
#define ATTN_SMEM_BYTES  (ATTN_SMEM_FLOATS * 4)

__global__ __launch_bounds__(256) void attn_kernel(
    const float* __restrict__ qkv, float* __restrict__ Y)
{
    extern __shared__ __align__(16) float sm[];
    float* Qs = sm;                              // [64][132], transposed (d-major)
    float* Ks = Qs + HDIM * QS_LD;               // [64][68],  transposed (d-major)
    float* Vs = Ks + HDIM * KS_LD;               // [64][68],  (k, d)
    float* Ps = Vs + BKV * VS_LD;                // [128][68], (q, k)

    const int tid = threadIdx.x;
    const int tx = tid & 15;                     // key / d-col group
    const int ty = tid >> 4;                     // query row group
    const int qt = blockIdx.x;                   // query tile
    const int bh = blockIdx.y;
    const int b  = bh >> 4;
    const int h  = bh & 15;

    const float* base = qkv + (size_t)b * SEQ * C3 + h * HDIM;

    // Load Q tile (rows qt*128..+127, d 0..63) transposed into Qs[d][r]
    for (int i = tid; i < BQ * 16; i += 256) {
        const int r  = i >> 4;
        const int d4 = (i & 15) * 4;
        float4 v = *(const float4*)(base + (size_t)(qt * BQ + r) * C3 + d4);
        Qs[(d4 + 0) * QS_LD + r] = v.x;
        Qs[(d4 + 1) * QS_LD + r] = v.y;
        Qs[(d4 + 2) * QS_LD + r] = v.z;
        Qs[(d4 + 3) * QS_LD + r] = v.w;
    }

    float m[8], l[8], acc[8][4];
    #pragma unroll
    for (int i = 0; i < 8; i++) {
        m[i] = -1e30f; l[i] = 0.0f;
        #pragma unroll
        for (int j = 0; j < 4; j++) acc[i][j] = 0.0f;
    }

    const int ktmax = 2 * qt + 1;
    for (int kt = 0; kt <= ktmax; kt++) {
        __syncthreads();   // prior PV done before overwriting K/V/P

        // Load K (transposed) and V tiles
        for (int i = tid; i < BKV * 16; i += 256) {
            const int r  = i >> 4;
            const int d4 = (i & 15) * 4;
            const float* kp = base + EMBD + (size_t)(kt * BKV + r) * C3 + d4;
            float4 kv = *(const float4*)kp;
            Ks[(d4 + 0) * KS_LD + r] = kv.x;
            Ks[(d4 + 1) * KS_LD + r] = kv.y;
            Ks[(d4 + 2) * KS_LD + r] = kv.z;
            Ks[(d4 + 3) * KS_LD + r] = kv.w;
            float4 vv = *(const float4*)(kp + EMBD);
            *(float4*)&Vs[r * VS_LD + d4] = vv;
        }
        __syncthreads();

        // S = Q @ K^T  (8x4 per thread)
        float s[8][4];
        #pragma unroll
        for (int i = 0; i < 8; i++)
            #pragma unroll
            for (int j = 0; j < 4; j++) s[i][j] = 0.0f;

        #pragma unroll 8
        for (int d = 0; d < HDIM; d++) {
            float4 q0 = *(const float4*)&Qs[d * QS_LD + ty * 8];
            float4 q1 = *(const float4*)&Qs[d * QS_LD + ty * 8 + 4];
            float4 kf = *(const float4*)&Ks[d * KS_LD + tx * 4];
            float qf[8] = {q0.x,q0.y,q0.z,q0.w,q1.x,q1.y,q1.z,q1.w};
            float kv[4] = {kf.x,kf.y,kf.z,kf.w};
            #pragma unroll
            for (int i = 0; i < 8; i++)
                #pragma unroll
                for (int j = 0; j < 4; j++)
                    s[i][j] = fmaf(qf[i], kv[j], s[i][j]);
        }

        const float scale = 0.125f;   // 1/sqrt(64)
        const bool need_mask = (kt >= 2 * qt);

        // Online softmax
        #pragma unroll
        for (int i = 0; i < 8; i++) {
            const int grow = qt * BQ + ty * 8 + i;
            float rmax = -1e30f;
            #pragma unroll
            for (int j = 0; j < 4; j++) {
                float v = s[i][j] * scale;
                if (need_mask && (kt * BKV + tx * 4 + j) > grow) v = -1e30f;
                s[i][j] = v;
                rmax = fmaxf(rmax, v);
            }
            #pragma unroll
            for (int o = 1; o < 16; o <<= 1)
                rmax = fmaxf(rmax, __shfl_xor_sync(0xffffffffu, rmax, o));
            const float mn = fmaxf(m[i], rmax);
            const float alpha = __expf(m[i] - mn);
            m[i] = mn;
            float rs = 0.0f;
            #pragma unroll
            for (int j = 0; j < 4; j++) {
                float p = __expf(s[i][j] - mn);
                Ps[(ty * 8 + i) * PS_LD + tx * 4 + j] = p;
                rs += p;
            }
            #pragma unroll
            for (int o = 1; o < 16; o <<= 1)
                rs += __shfl_xor_sync(0xffffffffu, rs, o);
            l[i] = l[i] * alpha + rs;
            #pragma unroll
            for (int j = 0; j < 4; j++) acc[i][j] *= alpha;
        }
        __syncthreads();

        // O += P @ V
        #pragma unroll 8
        for (int kk = 0; kk < BKV; kk++) {
            float4 vf4 = *(const float4*)&Vs[kk * VS_LD + tx * 4];
            float vf[4] = {vf4.x, vf4.y, vf4.z, vf4.w};
            float pf[8];
            #pragma unroll
            for (int i = 0; i < 8; i++) pf[i] = Ps[(ty * 8 + i) * PS_LD + kk];
            #pragma unroll
            for (int i = 0; i < 8; i++)
                #pragma unroll
                for (int j = 0; j < 4; j++)
                    acc[i][j] = fmaf(pf[i], vf[j], acc[i][j]);
        }
    }

    // Write output: Y[b, t, h*64 + d]
    float* yb = Y + ((size_t)b * SEQ + (size_t)qt * BQ) * EMBD + h * HDIM;
    #pragma unroll
    for (int i = 0; i < 8; i++) {
        const int r = ty * 8 + i;
        const float inv = 1.0f / l[i];
        float4 o;
        o.x = acc[i][0] * inv;
        o.y = acc[i][1] * inv;
        o.z = acc[i][2] * inv;
        o.w = acc[i][3] * inv;
        *(float4*)(yb + (size_t)r * EMBD + tx * 4) = o;
    }
}

// ---------------------------------------------------------------------------
extern "C" void kernel_launch(void* const* d_in, const int* in_sizes, int n_in,
                              void* d_out, int out_size)
{
    const float* x      = (const float*)d_in[0];
    const float* W_attn = (const float*)d_in[1];
    const float* b_attn = (const float*)d_in[2];
    const float* W_proj = (const float*)d_in[3];
    const float* b_proj = (const float*)d_in[4];
    float* out = (float*)d_out;

    float *qkv_ptr, *y_ptr;
    cudaGetSymbolAddress((void**)&qkv_ptr, g_qkv);
    cudaGetSymbolAddress((void**)&y_ptr, g_y);

    cudaFuncSetAttribute(attn_kernel,
                         cudaFuncAttributeMaxDynamicSharedMemorySize,
                         ATTN_SMEM_BYTES);

    // 1) QKV = x @ W_attn + b_attn
    {
        dim3 grid(C3 / 128, BT / 128);
        sgemm_bias<<<grid, 256>>>(x, W_attn, b_attn, qkv_ptr, BT, C3, EMBD);
    }
    // 2) causal flash attention
    {
        dim3 grid(SEQ / BQ, BATCH * NHEAD);
        attn_kernel<<<grid, 256, ATTN_SMEM_BYTES>>>(qkv_ptr, y_ptr);
    }
    // 3) out = y @ W_proj + b_proj
    {
        dim3 grid(EMBD / 128, BT / 128);
        sgemm_bias<<<grid, 256>>>(y_ptr, W_proj, b_proj, out, BT, EMBD, EMBD);
    }
}

// round 5
// speedup vs baseline: 1.6726x; 1.6726x over previous
#include <cuda_runtime.h>
#include <cuda_bf16.h>
#include <cstdint>

// ---------------------------------------------------------------------------
// Problem constants
// ---------------------------------------------------------------------------
#define BATCH 4
#define SEQ   2048
#define EMBD  1024
#define NHEAD 16
#define HDIM  64
#define BT    (BATCH*SEQ)        // 8192
#define C3    (3*EMBD)           // 3072

// ---------------------------------------------------------------------------
// Scratch (device globals — no allocation allowed)
// ---------------------------------------------------------------------------
__device__ float g_qkv[(size_t)BT * C3];    // [bt, 3C] interleaved q|k|v
__device__ float g_y[(size_t)BT * EMBD];    // attention output [b,t,c]

__device__ __nv_bfloat16 g_xh[(size_t)BT * EMBD];
__device__ __nv_bfloat16 g_xl[(size_t)BT * EMBD];
__device__ __nv_bfloat16 g_wah[(size_t)EMBD * C3];
__device__ __nv_bfloat16 g_wal[(size_t)EMBD * C3];
__device__ __nv_bfloat16 g_wph[(size_t)EMBD * EMBD];
__device__ __nv_bfloat16 g_wpl[(size_t)EMBD * EMBD];
__device__ __nv_bfloat16 g_yh[(size_t)BT * EMBD];
__device__ __nv_bfloat16 g_yl[(size_t)BT * EMBD];

// ---------------------------------------------------------------------------
// PTX helpers (sm_80+ portable: mma.sync / ldmatrix / cp.async)
// ---------------------------------------------------------------------------
__device__ __forceinline__ uint32_t smem_to_u32(const void* smem_ptr) {
    uint32_t addr;
    asm("{ .reg .u64 tmp; cvta.to.shared.u64 tmp, %1; cvt.u32.u64 %0, tmp; }"
        : "=r"(addr) : "l"(smem_ptr));
    return addr;
}

#define CP_ASYNC16(saddr, gptr) \
    asm volatile("cp.async.cg.shared.global [%0], [%1], 16;" \
        :: "r"(saddr), "l"(gptr) : "memory")
#define CP_ASYNC_COMMIT() asm volatile("cp.async.commit_group;" ::: "memory")
#define CP_ASYNC_WAIT0()  asm volatile("cp.async.wait_group 0;" ::: "memory")

#define LDMATRIX_X4(r0,r1,r2,r3, addr) \
    asm volatile("ldmatrix.sync.aligned.m8n8.x4.shared.b16 {%0,%1,%2,%3}, [%4];" \
        : "=r"(r0), "=r"(r1), "=r"(r2), "=r"(r3) : "r"(addr))

#define LDMATRIX_X4_T(r0,r1,r2,r3, addr) \
    asm volatile("ldmatrix.sync.aligned.m8n8.x4.trans.shared.b16 {%0,%1,%2,%3}, [%4];" \
        : "=r"(r0), "=r"(r1), "=r"(r2), "=r"(r3) : "r"(addr))

#define MMA_16816(d, a, b0v, b1v) \
    asm volatile( \
        "mma.sync.aligned.m16n8k16.row.col.f32.bf16.bf16.f32 " \
        "{%0,%1,%2,%3}, {%4,%5,%6,%7}, {%8,%9}, {%0,%1,%2,%3};" \
        : "+f"((d)[0]), "+f"((d)[1]), "+f"((d)[2]), "+f"((d)[3]) \
        : "r"((a)[0]), "r"((a)[1]), "r"((a)[2]), "r"((a)[3]), \
          "r"(b0v), "r"(b1v))

// ---------------------------------------------------------------------------
// Split fp32 -> (bf16 hi, bf16 lo) with lo = x - float(hi)
// ---------------------------------------------------------------------------
__global__ __launch_bounds__(256) void split_bf16(
    const float* __restrict__ src,
    __nv_bfloat16* __restrict__ hi, __nv_bfloat16* __restrict__ lo, int n4)
{
    int i = blockIdx.x * 256 + threadIdx.x;
    if (i >= n4) return;
    float4 v = ((const float4*)src)[i];
    float f[4] = {v.x, v.y, v.z, v.w};
    __nv_bfloat16 h[4], l[4];
    #pragma unroll
    for (int j = 0; j < 4; j++) {
        h[j] = __float2bfloat16(f[j]);
        float r = f[j] - __bfloat162float(h[j]);
        l[j] = __float2bfloat16(r);
    }
    __nv_bfloat162* H = (__nv_bfloat162*)hi;
    __nv_bfloat162* L = (__nv_bfloat162*)lo;
    H[2*i]     = __nv_bfloat162(h[0], h[1]);
    H[2*i + 1] = __nv_bfloat162(h[2], h[3]);
    L[2*i]     = __nv_bfloat162(l[0], l[1]);
    L[2*i + 1] = __nv_bfloat162(l[2], l[3]);
}

// ---------------------------------------------------------------------------
// mma.sync bf16x3 GEMM: C[M,N] = A@B + bias (fp32-accurate via hi/lo splits).
// Block tile 128x128, K-chunk 32 per split, 256 threads (8 warps of 64x32).
// cp.async double-buffered smem. HMMA m16n8k16, fp32 accumulate.
//
// Smem (bytes, per buffer):
//   A_hi [128][40] bf16 stride 80B  : off 0,     size 10240
//   A_lo                            : off 10240, size 10240
//   B_hi [32][136] bf16 stride 272B : off 20480, size 8704
//   B_lo                            : off 29184, size 8704
//   buffer stride 37888, x2 = 75776 bytes
// ---------------------------------------------------------------------------
#define GOFF_AH 0u
#define GOFF_AL 10240u
#define GOFF_BH 20480u
#define GOFF_BL 29184u
#define GBUF    37888u
#define GEMM_SMEM_BYTES (2u * GBUF)

__global__ __launch_bounds__(256) void gemm_mma_bf16x3(
    const __nv_bfloat16* __restrict__ Ah, const __nv_bfloat16* __restrict__ Al,
    const __nv_bfloat16* __restrict__ Bh, const __nv_bfloat16* __restrict__ Bl,
    const float* __restrict__ bias, float* __restrict__ Cout,
    int M, int N, int K)
{
    extern __shared__ __align__(16) char smem[];
    const uint32_t sb = smem_to_u32(smem);
    const int tid  = threadIdx.x;
    const int warp = tid >> 5;
    const int lane = tid & 31;
    const int wm = warp & 1;      // 0..1 -> m offset *64
    const int wn = warp >> 1;     // 0..3 -> n offset *32
    const int row0 = blockIdx.y * 128;
    const int col0 = blockIdx.x * 128;

    // global load mapping (per chunk): A: 4 thr/row x 64B; B: 16 thr/row x 256B
    const int ar = tid >> 2;             // 0..63 (+64 on 2nd pass)
    const int ac = (tid & 3) * 8;        // elem offset in k
    const int bkr = tid >> 4;            // 0..15 (+16 on 2nd pass)
    const int bnc = (tid & 15) * 8;      // elem offset in n

    const int nchunk = K >> 5;

    float acc[4][4][4];
    #pragma unroll
    for (int mt = 0; mt < 4; mt++)
        #pragma unroll
        for (int nt = 0; nt < 4; nt++)
            #pragma unroll
            for (int r = 0; r < 4; r++) acc[mt][nt][r] = 0.0f;

    // --- prefetch chunk 0 into buffer 0 ---
    {
        const int kc0 = 0;
        #pragma unroll
        for (int p = 0; p < 2; p++) {
            int r = ar + p * 64;
            CP_ASYNC16(sb + GOFF_AH + r*80 + ac*2,
                       Ah + (size_t)(row0 + r) * K + kc0 + ac);
            CP_ASYNC16(sb + GOFF_AL + r*80 + ac*2,
                       Al + (size_t)(row0 + r) * K + kc0 + ac);
            int kr = bkr + p * 16;
            CP_ASYNC16(sb + GOFF_BH + kr*272 + bnc*2,
                       Bh + (size_t)(kc0 + kr) * N + col0 + bnc);
            CP_ASYNC16(sb + GOFF_BL + kr*272 + bnc*2,
                       Bl + (size_t)(kc0 + kr) * N + col0 + bnc);
        }
        CP_ASYNC_COMMIT();
    }

    uint32_t buf = 0;
    for (int c = 0; c < nchunk; c++) {
        CP_ASYNC_WAIT0();
        __syncthreads();

        if (c + 1 < nchunk) {
            const uint32_t nb = sb + (buf ^ 1) * GBUF;
            const int kc0 = (c + 1) << 5;
            #pragma unroll
            for (int p = 0; p < 2; p++) {
                int r = ar + p * 64;
                CP_ASYNC16(nb + GOFF_AH + r*80 + ac*2,
                           Ah + (size_t)(row0 + r) * K + kc0 + ac);
                CP_ASYNC16(nb + GOFF_AL + r*80 + ac*2,
                           Al + (size_t)(row0 + r) * K + kc0 + ac);
                int kr = bkr + p * 16;
                CP_ASYNC16(nb + GOFF_BH + kr*272 + bnc*2,
                           Bh + (size_t)(kc0 + kr) * N + col0 + bnc);
                CP_ASYNC16(nb + GOFF_BL + kr*272 + bnc*2,
                           Bl + (size_t)(kc0 + kr) * N + col0 + bnc);
            }
            CP_ASYNC_COMMIT();
        }

        // --- compute current buffer ---
        const uint32_t cb = sb + buf * GBUF;
        #pragma unroll
        for (int s = 0; s < 2; s++) {
            uint32_t a_h[4][4], a_l[4][4];
            const int arow_base = wm * 64 + (lane & 15);
            const int acol = (s * 16 + (lane >> 4) * 8) * 2;   // byte offset
            #pragma unroll
            for (int mt = 0; mt < 4; mt++) {
                uint32_t off = (uint32_t)((arow_base + mt * 16) * 80 + acol);
                LDMATRIX_X4(a_h[mt][0], a_h[mt][1], a_h[mt][2], a_h[mt][3],
                            cb + GOFF_AH + off);
                LDMATRIX_X4(a_l[mt][0], a_l[mt][1], a_l[mt][2], a_l[mt][3],
                            cb + GOFF_AL + off);
            }
            uint32_t b_h[2][4], b_l[2][4];
            const int g = lane >> 3;
            const int krow = s * 16 + (g & 1) * 8 + (lane & 7);
            #pragma unroll
            for (int ntp = 0; ntp < 2; ntp++) {
                const int ncol = wn * 32 + ntp * 16 + (g >> 1) * 8;
                uint32_t off = (uint32_t)(krow * 272 + ncol * 2);
                LDMATRIX_X4_T(b_h[ntp][0], b_h[ntp][1], b_h[ntp][2], b_h[ntp][3],
                              cb + GOFF_BH + off);
                LDMATRIX_X4_T(b_l[ntp][0], b_l[ntp][1], b_l[ntp][2], b_l[ntp][3],
                              cb + GOFF_BL + off);
            }
            #pragma unroll
            for (int mt = 0; mt < 4; mt++) {
                #pragma unroll
                for (int nt = 0; nt < 4; nt++) {
                    const uint32_t bh0 = b_h[nt >> 1][(nt & 1) * 2];
                    const uint32_t bh1 = b_h[nt >> 1][(nt & 1) * 2 + 1];
                    const uint32_t bl0 = b_l[nt >> 1][(nt & 1) * 2];
                    const uint32_t bl1 = b_l[nt >> 1][(nt & 1) * 2 + 1];
                    MMA_16816(acc[mt][nt], a_h[mt], bh0, bh1);
                    MMA_16816(acc[mt][nt], a_h[mt], bl0, bl1);
                    MMA_16816(acc[mt][nt], a_l[mt], bh0, bh1);
                }
            }
        }
        buf ^= 1;
    }

    // --- epilogue: fragment layout -> global, + bias ---
    const int er = (lane >> 2);
    const int ec = (lane & 3) * 2;
    #pragma unroll
    for (int mt = 0; mt < 4; mt++) {
        #pragma unroll
        for (int nt = 0; nt < 4; nt++) {
            const int r  = row0 + wm * 64 + mt * 16 + er;
            const int cc = col0 + wn * 32 + nt * 8 + ec;
            float2 bv = *(const float2*)(bias + cc);
            float2 o0, o1;
            o0.x = acc[mt][nt][0] + bv.x;
            o0.y = acc[mt][nt][1] + bv.y;
            o1.x = acc[mt][nt][2] + bv.x;
            o1.y = acc[mt][nt][3] + bv.y;
            *(float2*)(Cout + (size_t)r * N + cc)       = o0;
            *(float2*)(Cout + (size_t)(r + 8) * N + cc) = o1;
        }
    }
}

// ---------------------------------------------------------------------------
// Flash attention (causal), fp32 — unchanged from passing baseline.
// ---------------------------------------------------------------------------
#define BQ  128
#define BKV 64
#define QS_LD  132
#define KS_LD  68
#define VS_LD  68
#define PS_LD  68
#define ATTN_SMEM_FLOATS (HDIM*QS_LD + HDIM*KS_LD + BKV*VS_LD + BQ*PS_LD)
#define ATTN_SMEM_BYTES  (ATTN_SMEM_FLOATS * 4)

__global__ __launch_bounds__(256) void attn_kernel(
    const float* __restrict__ qkv, float* __restrict__ Y)
{
    extern __shared__ __align__(16) float sm[];
    float* Qs = sm;
    float* Ks = Qs + HDIM * QS_LD;
    float* Vs = Ks + HDIM * KS_LD;
    float* Ps = Vs + BKV * VS_LD;

    const int tid = threadIdx.x;
    const int tx = tid & 15;
    const int ty = tid >> 4;
    const int qt = blockIdx.x;
    const int bh = blockIdx.y;
    const int b  = bh >> 4;
    const int h  = bh & 15;

    const float* base = qkv + (size_t)b * SEQ * C3 + h * HDIM;

    for (int i = tid; i < BQ * 16; i += 256) {
        const int r  = i >> 4;
        const int d4 = (i & 15) * 4;
        float4 v = *(const float4*)(base + (size_t)(qt * BQ + r) * C3 + d4);
        Qs[(d4 + 0) * QS_LD + r] = v.x;
        Qs[(d4 + 1) * QS_LD + r] = v.y;
        Qs[(d4 + 2) * QS_LD + r] = v.z;
        Qs[(d4 + 3) * QS_LD + r] = v.w;
    }

    float m[8], l[8], acc[8][4];
    #pragma unroll
    for (int i = 0; i < 8; i++) {
        m[i] = -1e30f; l[i] = 0.0f;
        #pragma unroll
        for (int j = 0; j < 4; j++) acc[i][j] = 0.0f;
    }

    const int ktmax = 2 * qt + 1;
    for (int kt = 0; kt <= ktmax; kt++) {
        __syncthreads();

        for (int i = tid; i < BKV * 16; i += 256) {
            const int r  = i >> 4;
            const int d4 = (i & 15) * 4;
            const float* kp = base + EMBD + (size_t)(kt * BKV + r) * C3 + d4;
            float4 kv = *(const float4*)kp;
            Ks[(d4 + 0) * KS_LD + r] = kv.x;
            Ks[(d4 + 1) * KS_LD + r] = kv.y;
            Ks[(d4 + 2) * KS_LD + r] = kv.z;
            Ks[(d4 + 3) * KS_LD + r] = kv.w;
            float4 vv = *(const float4*)(kp + EMBD);
            *(float4*)&Vs[r * VS_LD + d4] = vv;
        }
        __syncthreads();

        float s[8][4];
        #pragma unroll
        for (int i = 0; i < 8; i++)
            #pragma unroll
            for (int j = 0; j < 4; j++) s[i][j] = 0.0f;

        #pragma unroll 8
        for (int d = 0; d < HDIM; d++) {
            float4 q0 = *(const float4*)&Qs[d * QS_LD + ty * 8];
            float4 q1 = *(const float4*)&Qs[d * QS_LD + ty * 8 + 4];
            float4 kf = *(const float4*)&Ks[d * KS_LD + tx * 4];
            float qf[8] = {q0.x,q0.y,q0.z,q0.w,q1.x,q1.y,q1.z,q1.w};
            float kv[4] = {kf.x,kf.y,kf.z,kf.w};
            #pragma unroll
            for (int i = 0; i < 8; i++)
                #pragma unroll
                for (int j = 0; j < 4; j++)
                    s[i][j] = fmaf(qf[i], kv[j], s[i][j]);
        }

        const float scale = 0.125f;
        const bool need_mask = (kt >= 2 * qt);

        #pragma unroll
        for (int i = 0; i < 8; i++) {
            const int grow = qt * BQ + ty * 8 + i;
            float rmax = -1e30f;
            #pragma unroll
            for (int j = 0; j < 4; j++) {
                float v = s[i][j] * scale;
                if (need_mask && (kt * BKV + tx * 4 + j) > grow) v = -1e30f;
                s[i][j] = v;
                rmax = fmaxf(rmax, v);
            }
            #pragma unroll
            for (int o = 1; o < 16; o <<= 1)
                rmax = fmaxf(rmax, __shfl_xor_sync(0xffffffffu, rmax, o));
            const float mn = fmaxf(m[i], rmax);
            const float alpha = __expf(m[i] - mn);
            m[i] = mn;
            float rs = 0.0f;
            #pragma unroll
            for (int j = 0; j < 4; j++) {
                float p = __expf(s[i][j] - mn);
                Ps[(ty * 8 + i) * PS_LD + tx * 4 + j] = p;
                rs += p;
            }
            #pragma unroll
            for (int o = 1; o < 16; o <<= 1)
                rs += __shfl_xor_sync(0xffffffffu, rs, o);
            l[i] = l[i] * alpha + rs;
            #pragma unroll
            for (int j = 0; j < 4; j++) acc[i][j] *= alpha;
        }
        __syncthreads();

        #pragma unroll 8
        for (int kk = 0; kk < BKV; kk++) {
            float4 vf4 = *(const float4*)&Vs[kk * VS_LD + tx * 4];
            float vf[4] = {vf4.x, vf4.y, vf4.z, vf4.w};
            float pf[8];
            #pragma unroll
            for (int i = 0; i < 8; i++) pf[i] = Ps[(ty * 8 + i) * PS_LD + kk];
            #pragma unroll
            for (int i = 0; i < 8; i++)
                #pragma unroll
                for (int j = 0; j < 4; j++)
                    acc[i][j] = fmaf(pf[i], vf[j], acc[i][j]);
        }
    }

    float* yb = Y + ((size_t)b * SEQ + (size_t)qt * BQ) * EMBD + h * HDIM;
    #pragma unroll
    for (int i = 0; i < 8; i++) {
        const int r = ty * 8 + i;
        const float inv = 1.0f / l[i];
        float4 o;
        o.x = acc[i][0] * inv;
        o.y = acc[i][1] * inv;
        o.z = acc[i][2] * inv;
        o.w = acc[i][3] * inv;
        *(float4*)(yb + (size_t)r * EMBD + tx * 4) = o;
    }
}

// ---------------------------------------------------------------------------
extern "C" void kernel_launch(void* const* d_in, const int* in_sizes, int n_in,
                              void* d_out, int out_size)
{
    const float* x      = (const float*)d_in[0];
    const float* W_attn = (const float*)d_in[1];
    const float* b_attn = (const float*)d_in[2];
    const float* W_proj = (const float*)d_in[3];
    const float* b_proj = (const float*)d_in[4];
    float* out = (float*)d_out;

    float *qkv_p, *y_p;
    __nv_bfloat16 *xh, *xl, *wah, *wal, *wph, *wpl, *yh, *yl;
    cudaGetSymbolAddress((void**)&qkv_p, g_qkv);
    cudaGetSymbolAddress((void**)&y_p,   g_y);
    cudaGetSymbolAddress((void**)&xh,  g_xh);
    cudaGetSymbolAddress((void**)&xl,  g_xl);
    cudaGetSymbolAddress((void**)&wah, g_wah);
    cudaGetSymbolAddress((void**)&wal, g_wal);
    cudaGetSymbolAddress((void**)&wph, g_wph);
    cudaGetSymbolAddress((void**)&wpl, g_wpl);
    cudaGetSymbolAddress((void**)&yh,  g_yh);
    cudaGetSymbolAddress((void**)&yl,  g_yl);

    cudaFuncSetAttribute(attn_kernel,
                         cudaFuncAttributeMaxDynamicSharedMemorySize, ATTN_SMEM_BYTES);
    cudaFuncSetAttribute(gemm_mma_bf16x3,
                         cudaFuncAttributeMaxDynamicSharedMemorySize, GEMM_SMEM_BYTES);

    // 0) split inputs to bf16 hi/lo
    {
        int n4 = BT * EMBD / 4;
        split_bf16<<<(n4 + 255) / 256, 256>>>(x, xh, xl, n4);
        n4 = EMBD * C3 / 4;
        split_bf16<<<(n4 + 255) / 256, 256>>>(W_attn, wah, wal, n4);
        n4 = EMBD * EMBD / 4;
        split_bf16<<<(n4 + 255) / 256, 256>>>(W_proj, wph, wpl, n4);
    }
    // 1) QKV = x @ W_attn + b_attn   (HMMA bf16x3)
    {
        dim3 grid(C3 / 128, BT / 128);
        gemm_mma_bf16x3<<<grid, 256, GEMM_SMEM_BYTES>>>(xh, xl, wah, wal, b_attn,
                                                        qkv_p, BT, C3, EMBD);
    }
    // 2) causal flash attention (fp32)
    {
        dim3 grid(SEQ / BQ, BATCH * NHEAD);
        attn_kernel<<<grid, 256, ATTN_SMEM_BYTES>>>(qkv_p, y_p);
    }
    // 3) split y, then out = y @ W_proj + b_proj
    {
        int n4 = BT * EMBD / 4;
        split_bf16<<<(n4 + 255) / 256, 256>>>(y_p, yh, yl, n4);
        dim3 grid(EMBD / 128, BT / 128);
        gemm_mma_bf16x3<<<grid, 256, GEMM_SMEM_BYTES>>>(yh, yl, wph, wpl, b_proj,
                                                        out, BT, EMBD, EMBD);
    }
}

// round 6
// speedup vs baseline: 2.6997x; 1.6141x over previous
#include <cuda_runtime.h>
#include <cuda_bf16.h>
#include <cstdint>

// ---------------------------------------------------------------------------
// Problem constants
// ---------------------------------------------------------------------------
#define BATCH 4
#define SEQ   2048
#define EMBD  1024
#define NHEAD 16
#define HDIM  64
#define BT    (BATCH*SEQ)        // 8192
#define C3    (3*EMBD)           // 3072

// ---------------------------------------------------------------------------
// Scratch (device globals — no allocation allowed)
// ---------------------------------------------------------------------------
__device__ __nv_bfloat16 g_qkvh[(size_t)BT * C3];
__device__ __nv_bfloat16 g_qkvl[(size_t)BT * C3];
__device__ __nv_bfloat16 g_xh[(size_t)BT * EMBD];
__device__ __nv_bfloat16 g_xl[(size_t)BT * EMBD];
__device__ __nv_bfloat16 g_wah[(size_t)EMBD * C3];
__device__ __nv_bfloat16 g_wal[(size_t)EMBD * C3];
__device__ __nv_bfloat16 g_wph[(size_t)EMBD * EMBD];
__device__ __nv_bfloat16 g_wpl[(size_t)EMBD * EMBD];
__device__ __nv_bfloat16 g_yh[(size_t)BT * EMBD];
__device__ __nv_bfloat16 g_yl[(size_t)BT * EMBD];

// ---------------------------------------------------------------------------
// PTX helpers (sm_80+ portable: mma.sync / ldmatrix / cp.async)
// ---------------------------------------------------------------------------
__device__ __forceinline__ uint32_t smem_to_u32(const void* smem_ptr) {
    uint32_t addr;
    asm("{ .reg .u64 tmp; cvta.to.shared.u64 tmp, %1; cvt.u32.u64 %0, tmp; }"
        : "=r"(addr) : "l"(smem_ptr));
    return addr;
}

#define CP_ASYNC16(saddr, gptr) \
    asm volatile("cp.async.cg.shared.global [%0], [%1], 16;" \
        :: "r"(saddr), "l"(gptr) : "memory")
#define CP_ASYNC_COMMIT() asm volatile("cp.async.commit_group;" ::: "memory")
#define CP_ASYNC_WAIT0()  asm volatile("cp.async.wait_group 0;" ::: "memory")
#define CP_ASYNC_WAIT1()  asm volatile("cp.async.wait_group 1;" ::: "memory")

#define LDMATRIX_X4(r0,r1,r2,r3, addr) \
    asm volatile("ldmatrix.sync.aligned.m8n8.x4.shared.b16 {%0,%1,%2,%3}, [%4];" \
        : "=r"(r0), "=r"(r1), "=r"(r2), "=r"(r3) : "r"(addr))

#define LDMATRIX_X4_T(r0,r1,r2,r3, addr) \
    asm volatile("ldmatrix.sync.aligned.m8n8.x4.trans.shared.b16 {%0,%1,%2,%3}, [%4];" \
        : "=r"(r0), "=r"(r1), "=r"(r2), "=r"(r3) : "r"(addr))

#define MMA_16816(d, a, b0v, b1v) \
    asm volatile( \
        "mma.sync.aligned.m16n8k16.row.col.f32.bf16.bf16.f32 " \
        "{%0,%1,%2,%3}, {%4,%5,%6,%7}, {%8,%9}, {%0,%1,%2,%3};" \
        : "+f"((d)[0]), "+f"((d)[1]), "+f"((d)[2]), "+f"((d)[3]) \
        : "r"((a)[0]), "r"((a)[1]), "r"((a)[2]), "r"((a)[3]), \
          "r"(b0v), "r"(b1v))

// split two fp32 into packed bf16x2 hi and lo
__device__ __forceinline__ void split2(float a, float b, uint32_t& h, uint32_t& l) {
    __nv_bfloat162 hh = __floats2bfloat162_rn(a, b);
    float2 hf = __bfloat1622float2(hh);
    __nv_bfloat162 ll = __floats2bfloat162_rn(a - hf.x, b - hf.y);
    h = *(uint32_t*)&hh;
    l = *(uint32_t*)&ll;
}

// ---------------------------------------------------------------------------
// Split fp32 -> (bf16 hi, bf16 lo)
// ---------------------------------------------------------------------------
__global__ __launch_bounds__(256) void split_bf16(
    const float* __restrict__ src,
    __nv_bfloat16* __restrict__ hi, __nv_bfloat16* __restrict__ lo, int n4)
{
    int i = blockIdx.x * 256 + threadIdx.x;
    if (i >= n4) return;
    float4 v = ((const float4*)src)[i];
    uint32_t h0, l0, h1, l1;
    split2(v.x, v.y, h0, l0);
    split2(v.z, v.w, h1, l1);
    ((uint32_t*)hi)[2*i]     = h0;
    ((uint32_t*)hi)[2*i + 1] = h1;
    ((uint32_t*)lo)[2*i]     = l0;
    ((uint32_t*)lo)[2*i + 1] = l1;
}

// ---------------------------------------------------------------------------
// mma.sync bf16x3 GEMM, 128x128 tile, 8 warps, cp.async double buffer.
// SPLIT_OUT=0: fp32 out (+bias). SPLIT_OUT=1: bf16 hi/lo out (+bias).
// ---------------------------------------------------------------------------
#define GOFF_AH 0u
#define GOFF_AL 10240u
#define GOFF_BH 20480u
#define GOFF_BL 29184u
#define GBUF    37888u
#define GEMM_SMEM_BYTES (2u * GBUF)

template<int SPLIT_OUT>
__global__ __launch_bounds__(256) void gemm_mma_bf16x3(
    const __nv_bfloat16* __restrict__ Ah, const __nv_bfloat16* __restrict__ Al,
    const __nv_bfloat16* __restrict__ Bh, const __nv_bfloat16* __restrict__ Bl,
    const float* __restrict__ bias, float* __restrict__ Cout,
    __nv_bfloat16* __restrict__ Ch, __nv_bfloat16* __restrict__ Cl,
    int M, int N, int K)
{
    extern __shared__ __align__(16) char smem[];
    const uint32_t sb = smem_to_u32(smem);
    const int tid  = threadIdx.x;
    const int warp = tid >> 5;
    const int lane = tid & 31;
    const int wm = warp & 1;
    const int wn = warp >> 1;
    const int row0 = blockIdx.y * 128;
    const int col0 = blockIdx.x * 128;

    const int ar = tid >> 2;
    const int ac = (tid & 3) * 8;
    const int bkr = tid >> 4;
    const int bnc = (tid & 15) * 8;

    const int nchunk = K >> 5;

    float acc[4][4][4];
    #pragma unroll
    for (int mt = 0; mt < 4; mt++)
        #pragma unroll
        for (int nt = 0; nt < 4; nt++)
            #pragma unroll
            for (int r = 0; r < 4; r++) acc[mt][nt][r] = 0.0f;

    {
        #pragma unroll
        for (int p = 0; p < 2; p++) {
            int r = ar + p * 64;
            CP_ASYNC16(sb + GOFF_AH + r*80 + ac*2, Ah + (size_t)(row0 + r) * K + ac);
            CP_ASYNC16(sb + GOFF_AL + r*80 + ac*2, Al + (size_t)(row0 + r) * K + ac);
            int kr = bkr + p * 16;
            CP_ASYNC16(sb + GOFF_BH + kr*272 + bnc*2, Bh + (size_t)kr * N + col0 + bnc);
            CP_ASYNC16(sb + GOFF_BL + kr*272 + bnc*2, Bl + (size_t)kr * N + col0 + bnc);
        }
        CP_ASYNC_COMMIT();
    }

    uint32_t buf = 0;
    for (int c = 0; c < nchunk; c++) {
        CP_ASYNC_WAIT0();
        __syncthreads();

        if (c + 1 < nchunk) {
            const uint32_t nb = sb + (buf ^ 1) * GBUF;
            const int kc0 = (c + 1) << 5;
            #pragma unroll
            for (int p = 0; p < 2; p++) {
                int r = ar + p * 64;
                CP_ASYNC16(nb + GOFF_AH + r*80 + ac*2, Ah + (size_t)(row0 + r) * K + kc0 + ac);
                CP_ASYNC16(nb + GOFF_AL + r*80 + ac*2, Al + (size_t)(row0 + r) * K + kc0 + ac);
                int kr = bkr + p * 16;
                CP_ASYNC16(nb + GOFF_BH + kr*272 + bnc*2, Bh + (size_t)(kc0 + kr) * N + col0 + bnc);
                CP_ASYNC16(nb + GOFF_BL + kr*272 + bnc*2, Bl + (size_t)(kc0 + kr) * N + col0 + bnc);
            }
            CP_ASYNC_COMMIT();
        }

        const uint32_t cb = sb + buf * GBUF;
        #pragma unroll
        for (int s = 0; s < 2; s++) {
            uint32_t a_h[4][4], a_l[4][4];
            const int arow_base = wm * 64 + (lane & 15);
            const int acol = (s * 16 + (lane >> 4) * 8) * 2;
            #pragma unroll
            for (int mt = 0; mt < 4; mt++) {
                uint32_t off = (uint32_t)((arow_base + mt * 16) * 80 + acol);
                LDMATRIX_X4(a_h[mt][0], a_h[mt][1], a_h[mt][2], a_h[mt][3], cb + GOFF_AH + off);
                LDMATRIX_X4(a_l[mt][0], a_l[mt][1], a_l[mt][2], a_l[mt][3], cb + GOFF_AL + off);
            }
            uint32_t b_h[2][4], b_l[2][4];
            const int g = lane >> 3;
            const int krow = s * 16 + (g & 1) * 8 + (lane & 7);
            #pragma unroll
            for (int ntp = 0; ntp < 2; ntp++) {
                const int ncol = wn * 32 + ntp * 16 + (g >> 1) * 8;
                uint32_t off = (uint32_t)(krow * 272 + ncol * 2);
                LDMATRIX_X4_T(b_h[ntp][0], b_h[ntp][1], b_h[ntp][2], b_h[ntp][3], cb + GOFF_BH + off);
                LDMATRIX_X4_T(b_l[ntp][0], b_l[ntp][1], b_l[ntp][2], b_l[ntp][3], cb + GOFF_BL + off);
            }
            #pragma unroll
            for (int mt = 0; mt < 4; mt++) {
                #pragma unroll
                for (int nt = 0; nt < 4; nt++) {
                    const uint32_t bh0 = b_h[nt >> 1][(nt & 1) * 2];
                    const uint32_t bh1 = b_h[nt >> 1][(nt & 1) * 2 + 1];
                    const uint32_t bl0 = b_l[nt >> 1][(nt & 1) * 2];
                    const uint32_t bl1 = b_l[nt >> 1][(nt & 1) * 2 + 1];
                    MMA_16816(acc[mt][nt], a_h[mt], bh0, bh1);
                    MMA_16816(acc[mt][nt], a_h[mt], bl0, bl1);
                    MMA_16816(acc[mt][nt], a_l[mt], bh0, bh1);
                }
            }
        }
        buf ^= 1;
    }

    const int er = (lane >> 2);
    const int ec = (lane & 3) * 2;
    #pragma unroll
    for (int mt = 0; mt < 4; mt++) {
        #pragma unroll
        for (int nt = 0; nt < 4; nt++) {
            const int r  = row0 + wm * 64 + mt * 16 + er;
            const int cc = col0 + wn * 32 + nt * 8 + ec;
            float2 bv = *(const float2*)(bias + cc);
            float o0x = acc[mt][nt][0] + bv.x;
            float o0y = acc[mt][nt][1] + bv.y;
            float o1x = acc[mt][nt][2] + bv.x;
            float o1y = acc[mt][nt][3] + bv.y;
            if (SPLIT_OUT) {
                uint32_t h0, l0, h1, l1;
                split2(o0x, o0y, h0, l0);
                split2(o1x, o1y, h1, l1);
                *(uint32_t*)(Ch + (size_t)r * N + cc)       = h0;
                *(uint32_t*)(Cl + (size_t)r * N + cc)       = l0;
                *(uint32_t*)(Ch + (size_t)(r + 8) * N + cc) = h1;
                *(uint32_t*)(Cl + (size_t)(r + 8) * N + cc) = l1;
            } else {
                *(float2*)(Cout + (size_t)r * N + cc)       = make_float2(o0x, o0y);
                *(float2*)(Cout + (size_t)(r + 8) * N + cc) = make_float2(o1x, o1y);
            }
        }
    }
}

// ---------------------------------------------------------------------------
// Flash attention (causal) with mma.sync bf16x3.
// CTA: 8 warps, BQ=128 queries of one (b,h); warp owns m16 rows.
// KV tiles of 64, cp.async double-buffered K/V hi/lo smem.
// Row stride 144B (72 bf16) — conflict-free ldmatrix.
// ---------------------------------------------------------------------------
#define BKV 64
#define AROW 144              // bytes per smem row
#define OKH 0u
#define OKL 9216u
#define OVH 18432u
#define OVL 27648u
#define ABUF 36864u
#define ATTN_SMEM_BYTES (2u * ABUF)

__global__ __launch_bounds__(256) void attn_mma(
    const __nv_bfloat16* __restrict__ qkvh, const __nv_bfloat16* __restrict__ qkvl,
    __nv_bfloat16* __restrict__ Yh, __nv_bfloat16* __restrict__ Yl)
{
    extern __shared__ __align__(16) char smem[];
    const uint32_t sb = smem_to_u32(smem);
    const int tid  = threadIdx.x;
    const int warp = tid >> 5;
    const int lane = tid & 31;

    const int qt = (int)(gridDim.x - 1 - blockIdx.x);   // heavy tiles first
    const int bh = blockIdx.y;
    const int b  = bh >> 4;
    const int h  = bh & 15;

    const size_t rowbase = (size_t)b * SEQ * C3 + h * HDIM;
    const __nv_bfloat16* qh_g = qkvh + rowbase;
    const __nv_bfloat16* ql_g = qkvl + rowbase;
    const __nv_bfloat16* kh_g = qkvh + rowbase + EMBD;
    const __nv_bfloat16* kl_g = qkvl + rowbase + EMBD;
    const __nv_bfloat16* vh_g = qkvh + rowbase + 2 * EMBD;
    const __nv_bfloat16* vl_g = qkvl + rowbase + 2 * EMBD;

    // ---- stage Q (128 rows x 64) hi/lo into smem, then to registers ----
    {
        #pragma unroll
        for (int it = 0; it < 4; it++) {
            int i = tid + it * 256;
            int row = i >> 3, ch = i & 7;
            const size_t go = (size_t)(qt * 128 + row) * C3 + ch * 8;
            CP_ASYNC16(sb + row * AROW + ch * 16,         qh_g + go);
            CP_ASYNC16(sb + 18432 + row * AROW + ch * 16, ql_g + go);
        }
        CP_ASYNC_COMMIT();
        CP_ASYNC_WAIT0();
        __syncthreads();
    }

    uint32_t aqh[4][4], aql[4][4];
    {
        const int arow = warp * 16 + (lane & 15);
        const int acby = (lane >> 4) * 16;
        #pragma unroll
        for (int kt4 = 0; kt4 < 4; kt4++) {
            uint32_t off = (uint32_t)(arow * AROW + kt4 * 32 + acby);
            LDMATRIX_X4(aqh[kt4][0], aqh[kt4][1], aqh[kt4][2], aqh[kt4][3], sb + off);
            LDMATRIX_X4(aql[kt4][0], aql[kt4][1], aql[kt4][2], aql[kt4][3], sb + 18432 + off);
        }
    }
    __syncthreads();   // done reading Q smem before K/V overwrite

    // ---- softmax state + O accumulators ----
    float m0 = -1e30f, m1 = -1e30f, l0 = 0.0f, l1 = 0.0f;
    float o[8][4];
    #pragma unroll
    for (int nt = 0; nt < 8; nt++)
        #pragma unroll
        for (int r = 0; r < 4; r++) o[nt][r] = 0.0f;

    const int nkv = 2 * qt + 2;

    // prefetch KV tiles 0 and 1
    #pragma unroll
    for (int pf = 0; pf < 2; pf++) {
        if (pf < nkv) {
            const uint32_t dst = sb + pf * ABUF;
            #pragma unroll
            for (int it = 0; it < 2; it++) {
                int i = tid + it * 256;
                int row = i >> 3, ch = i & 7;
                const size_t go = (size_t)(pf * BKV + row) * C3 + ch * 8;
                const uint32_t so = row * AROW + ch * 16;
                CP_ASYNC16(dst + OKH + so, kh_g + go);
                CP_ASYNC16(dst + OKL + so, kl_g + go);
                CP_ASYNC16(dst + OVH + so, vh_g + go);
                CP_ASYNC16(dst + OVL + so, vl_g + go);
            }
            CP_ASYNC_COMMIT();
        }
    }

    const float scale = 0.125f;  // 1/sqrt(64)

    for (int kt = 0; kt < nkv; kt++) {
        if (kt + 1 < nkv) { CP_ASYNC_WAIT1(); } else { CP_ASYNC_WAIT0(); }
        __syncthreads();

        const uint32_t cb = sb + (kt & 1) * ABUF;

        // ---- S = Qh*Kh^T + Qh*Kl^T + Ql*Kh^T  (m16 x n64, k=64) ----
        float s[8][4];
        #pragma unroll
        for (int nt = 0; nt < 8; nt++)
            #pragma unroll
            for (int r = 0; r < 4; r++) s[nt][r] = 0.0f;

        const int g = lane >> 3;
        #pragma unroll
        for (int kt4 = 0; kt4 < 4; kt4++) {
            uint32_t bkh[4][4], bkl[4][4];
            #pragma unroll
            for (int nt16 = 0; nt16 < 4; nt16++) {
                const int nrow = nt16 * 16 + (g & 1) * 8 + (lane & 7);
                const uint32_t off = (uint32_t)(nrow * AROW + kt4 * 32 + (g >> 1) * 16);
                LDMATRIX_X4(bkh[nt16][0], bkh[nt16][1], bkh[nt16][2], bkh[nt16][3], cb + OKH + off);
                LDMATRIX_X4(bkl[nt16][0], bkl[nt16][1], bkl[nt16][2], bkl[nt16][3], cb + OKL + off);
            }
            #pragma unroll
            for (int nt16 = 0; nt16 < 4; nt16++) {
                #pragma unroll
                for (int hv = 0; hv < 2; hv++) {
                    const int nt8 = nt16 * 2 + hv;
                    MMA_16816(s[nt8], aqh[kt4], bkh[nt16][hv], bkh[nt16][2 + hv]);
                    MMA_16816(s[nt8], aqh[kt4], bkl[nt16][hv], bkl[nt16][2 + hv]);
                    MMA_16816(s[nt8], aql[kt4], bkh[nt16][hv], bkh[nt16][2 + hv]);
                }
            }
        }

        // ---- online softmax ----
        const bool need_mask = (kt >= 2 * qt);
        const int r0g = qt * 128 + warp * 16 + (lane >> 2);
        const int r1g = r0g + 8;
        float rmax0 = -1e30f, rmax1 = -1e30f;
        #pragma unroll
        for (int nt = 0; nt < 8; nt++) {
            #pragma unroll
            for (int j = 0; j < 2; j++) {
                const int kc = kt * BKV + nt * 8 + (lane & 3) * 2 + j;
                float v0 = s[nt][j] * scale;
                float v1 = s[nt][2 + j] * scale;
                if (need_mask) {
                    if (kc > r0g) v0 = -1e30f;
                    if (kc > r1g) v1 = -1e30f;
                }
                s[nt][j] = v0;     rmax0 = fmaxf(rmax0, v0);
                s[nt][2 + j] = v1; rmax1 = fmaxf(rmax1, v1);
            }
        }
        rmax0 = fmaxf(rmax0, __shfl_xor_sync(0xffffffffu, rmax0, 1));
        rmax0 = fmaxf(rmax0, __shfl_xor_sync(0xffffffffu, rmax0, 2));
        rmax1 = fmaxf(rmax1, __shfl_xor_sync(0xffffffffu, rmax1, 1));
        rmax1 = fmaxf(rmax1, __shfl_xor_sync(0xffffffffu, rmax1, 2));

        const float mn0 = fmaxf(m0, rmax0);
        const float mn1 = fmaxf(m1, rmax1);
        const float alpha0 = __expf(m0 - mn0);
        const float alpha1 = __expf(m1 - mn1);
        m0 = mn0; m1 = mn1;

        float ps0 = 0.0f, ps1 = 0.0f;
        #pragma unroll
        for (int nt = 0; nt < 8; nt++) {
            #pragma unroll
            for (int j = 0; j < 2; j++) {
                float p0 = __expf(s[nt][j] - mn0);
                float p1 = __expf(s[nt][2 + j] - mn1);
                s[nt][j] = p0;     ps0 += p0;
                s[nt][2 + j] = p1; ps1 += p1;
            }
        }
        ps0 += __shfl_xor_sync(0xffffffffu, ps0, 1);
        ps0 += __shfl_xor_sync(0xffffffffu, ps0, 2);
        ps1 += __shfl_xor_sync(0xffffffffu, ps1, 1);
        ps1 += __shfl_xor_sync(0xffffffffu, ps1, 2);
        l0 = l0 * alpha0 + ps0;
        l1 = l1 * alpha1 + ps1;

        #pragma unroll
        for (int nt = 0; nt < 8; nt++) {
            o[nt][0] *= alpha0; o[nt][1] *= alpha0;
            o[nt][2] *= alpha1; o[nt][3] *= alpha1;
        }

        // ---- pack P -> bf16 hi/lo A-fragments (C-frag == A-frag mapping) ----
        uint32_t aph[4][4], apl[4][4];
        #pragma unroll
        for (int pt = 0; pt < 4; pt++) {
            split2(s[2*pt][0],   s[2*pt][1],   aph[pt][0], apl[pt][0]);
            split2(s[2*pt][2],   s[2*pt][3],   aph[pt][1], apl[pt][1]);
            split2(s[2*pt+1][0], s[2*pt+1][1], aph[pt][2], apl[pt][2]);
            split2(s[2*pt+1][2], s[2*pt+1][3], aph[pt][3], apl[pt][3]);
        }

        // ---- O += P @ V ----
        #pragma unroll
        for (int pt = 0; pt < 4; pt++) {
            uint32_t bvh[4][4], bvl[4][4];
            #pragma unroll
            for (int nt16 = 0; nt16 < 4; nt16++) {
                const int krow = pt * 16 + (g & 1) * 8 + (lane & 7);
                const uint32_t off = (uint32_t)(krow * AROW + nt16 * 32 + (g >> 1) * 16);
                LDMATRIX_X4_T(bvh[nt16][0], bvh[nt16][1], bvh[nt16][2], bvh[nt16][3], cb + OVH + off);
                LDMATRIX_X4_T(bvl[nt16][0], bvl[nt16][1], bvl[nt16][2], bvl[nt16][3], cb + OVL + off);
            }
            #pragma unroll
            for (int nt16 = 0; nt16 < 4; nt16++) {
                #pragma unroll
                for (int hv = 0; hv < 2; hv++) {
                    const int nt8 = nt16 * 2 + hv;
                    MMA_16816(o[nt8], aph[pt], bvh[nt16][hv * 2], bvh[nt16][hv * 2 + 1]);
                    MMA_16816(o[nt8], aph[pt], bvl[nt16][hv * 2], bvl[nt16][hv * 2 + 1]);
                    MMA_16816(o[nt8], apl[pt], bvh[nt16][hv * 2], bvh[nt16][hv * 2 + 1]);
                }
            }
        }

        __syncthreads();   // all warps done with this buffer

        if (kt + 2 < nkv) {
            const uint32_t dst = sb + (kt & 1) * ABUF;
            #pragma unroll
            for (int it = 0; it < 2; it++) {
                int i = tid + it * 256;
                int row = i >> 3, ch = i & 7;
                const size_t go = (size_t)((kt + 2) * BKV + row) * C3 + ch * 8;
                const uint32_t so = row * AROW + ch * 16;
                CP_ASYNC16(dst + OKH + so, kh_g + go);
                CP_ASYNC16(dst + OKL + so, kl_g + go);
                CP_ASYNC16(dst + OVH + so, vh_g + go);
                CP_ASYNC16(dst + OVL + so, vl_g + go);
            }
            CP_ASYNC_COMMIT();
        }
    }

    // ---- epilogue: normalize, split to bf16 hi/lo, store ----
    const float inv0 = 1.0f / l0;
    const float inv1 = 1.0f / l1;
    const int tr0 = qt * 128 + warp * 16 + (lane >> 2);
    const size_t ybase = (size_t)b * SEQ * EMBD + h * HDIM;
    #pragma unroll
    for (int nt = 0; nt < 8; nt++) {
        const int col = nt * 8 + (lane & 3) * 2;
        uint32_t h0, lo0, h1, lo1;
        split2(o[nt][0] * inv0, o[nt][1] * inv0, h0, lo0);
        split2(o[nt][2] * inv1, o[nt][3] * inv1, h1, lo1);
        *(uint32_t*)(Yh + ybase + (size_t)tr0 * EMBD + col)       = h0;
        *(uint32_t*)(Yl + ybase + (size_t)tr0 * EMBD + col)       = lo0;
        *(uint32_t*)(Yh + ybase + (size_t)(tr0 + 8) * EMBD + col) = h1;
        *(uint32_t*)(Yl + ybase + (size_t)(tr0 + 8) * EMBD + col) = lo1;
    }
}

// ---------------------------------------------------------------------------
extern "C" void kernel_launch(void* const* d_in, const int* in_sizes, int n_in,
                              void* d_out, int out_size)
{
    const float* x      = (const float*)d_in[0];
    const float* W_attn = (const float*)d_in[1];
    const float* b_attn = (const float*)d_in[2];
    const float* W_proj = (const float*)d_in[3];
    const float* b_proj = (const float*)d_in[4];
    float* out = (float*)d_out;

    __nv_bfloat16 *qkvh, *qkvl, *xh, *xl, *wah, *wal, *wph, *wpl, *yh, *yl;
    cudaGetSymbolAddress((void**)&qkvh, g_qkvh);
    cudaGetSymbolAddress((void**)&qkvl, g_qkvl);
    cudaGetSymbolAddress((void**)&xh,  g_xh);
    cudaGetSymbolAddress((void**)&xl,  g_xl);
    cudaGetSymbolAddress((void**)&wah, g_wah);
    cudaGetSymbolAddress((void**)&wal, g_wal);
    cudaGetSymbolAddress((void**)&wph, g_wph);
    cudaGetSymbolAddress((void**)&wpl, g_wpl);
    cudaGetSymbolAddress((void**)&yh,  g_yh);
    cudaGetSymbolAddress((void**)&yl,  g_yl);

    cudaFuncSetAttribute(gemm_mma_bf16x3<0>,
                         cudaFuncAttributeMaxDynamicSharedMemorySize, GEMM_SMEM_BYTES);
    cudaFuncSetAttribute(gemm_mma_bf16x3<1>,
                         cudaFuncAttributeMaxDynamicSharedMemorySize, GEMM_SMEM_BYTES);
    cudaFuncSetAttribute(attn_mma,
                         cudaFuncAttributeMaxDynamicSharedMemorySize, ATTN_SMEM_BYTES);

    // 0) split inputs
    {
        int n4 = BT * EMBD / 4;
        split_bf16<<<(n4 + 255) / 256, 256>>>(x, xh, xl, n4);
        n4 = EMBD * C3 / 4;
        split_bf16<<<(n4 + 255) / 256, 256>>>(W_attn, wah, wal, n4);
        n4 = EMBD * EMBD / 4;
        split_bf16<<<(n4 + 255) / 256, 256>>>(W_proj, wph, wpl, n4);
    }
    // 1) QKV GEMM -> bf16 hi/lo qkv (bias fused, split fused)
    {
        dim3 grid(C3 / 128, BT / 128);
        gemm_mma_bf16x3<1><<<grid, 256, GEMM_SMEM_BYTES>>>(
            xh, xl, wah, wal, b_attn, nullptr, qkvh, qkvl, BT, C3, EMBD);
    }
    // 2) causal flash attention (mma.sync bf16x3) -> bf16 hi/lo y
    {
        dim3 grid(SEQ / 128, BATCH * NHEAD);
        attn_mma<<<grid, 256, ATTN_SMEM_BYTES>>>(qkvh, qkvl, yh, yl);
    }
    // 3) proj GEMM -> fp32 out
    {
        dim3 grid(EMBD / 128, BT / 128);
        gemm_mma_bf16x3<0><<<grid, 256, GEMM_SMEM_BYTES>>>(
            yh, yl, wph, wpl, b_proj, out, nullptr, nullptr, BT, EMBD, EMBD);
    }
}

// round 9
// speedup vs baseline: 2.7824x; 1.0306x over previous
#include <cuda_runtime.h>
#include <cuda_bf16.h>
#include <cstdint>

// ---------------------------------------------------------------------------
// Problem constants
// ---------------------------------------------------------------------------
#define BATCH 4
#define SEQ   2048
#define EMBD  1024
#define NHEAD 16
#define HDIM  64
#define BT    (BATCH*SEQ)        // 8192
#define C3    (3*EMBD)           // 3072

// ---------------------------------------------------------------------------
// Scratch (device globals — no allocation allowed)
// ---------------------------------------------------------------------------
__device__ __nv_bfloat16 g_qkvh[(size_t)BT * C3];
__device__ __nv_bfloat16 g_qkvl[(size_t)BT * C3];
__device__ __nv_bfloat16 g_xh[(size_t)BT * EMBD];
__device__ __nv_bfloat16 g_xl[(size_t)BT * EMBD];
__device__ __nv_bfloat16 g_wah[(size_t)EMBD * C3];
__device__ __nv_bfloat16 g_wal[(size_t)EMBD * C3];
__device__ __nv_bfloat16 g_wph[(size_t)EMBD * EMBD];
__device__ __nv_bfloat16 g_wpl[(size_t)EMBD * EMBD];
__device__ __nv_bfloat16 g_yh[(size_t)BT * EMBD];
__device__ __nv_bfloat16 g_yl[(size_t)BT * EMBD];

// ---------------------------------------------------------------------------
// PTX helpers (sm_80+ portable: mma.sync / ldmatrix / cp.async)
// ---------------------------------------------------------------------------
__device__ __forceinline__ uint32_t smem_to_u32(const void* smem_ptr) {
    uint32_t addr;
    asm("{ .reg .u64 tmp; cvta.to.shared.u64 tmp, %1; cvt.u32.u64 %0, tmp; }"
        : "=r"(addr) : "l"(smem_ptr));
    return addr;
}

#define CP_ASYNC16(saddr, gptr) \
    asm volatile("cp.async.cg.shared.global [%0], [%1], 16;" \
        :: "r"(saddr), "l"(gptr) : "memory")
#define CP_ASYNC_COMMIT() asm volatile("cp.async.commit_group;" ::: "memory")
#define CP_ASYNC_WAIT0()  asm volatile("cp.async.wait_group 0;" ::: "memory")
#define CP_ASYNC_WAIT1()  asm volatile("cp.async.wait_group 1;" ::: "memory")

#define LDMATRIX_X4(r0,r1,r2,r3, addr) \
    asm volatile("ldmatrix.sync.aligned.m8n8.x4.shared.b16 {%0,%1,%2,%3}, [%4];" \
        : "=r"(r0), "=r"(r1), "=r"(r2), "=r"(r3) : "r"(addr))

#define LDMATRIX_X4_T(r0,r1,r2,r3, addr) \
    asm volatile("ldmatrix.sync.aligned.m8n8.x4.trans.shared.b16 {%0,%1,%2,%3}, [%4];" \
        : "=r"(r0), "=r"(r1), "=r"(r2), "=r"(r3) : "r"(addr))

#define MMA_16816(d, a, b0v, b1v) \
    asm volatile( \
        "mma.sync.aligned.m16n8k16.row.col.f32.bf16.bf16.f32 " \
        "{%0,%1,%2,%3}, {%4,%5,%6,%7}, {%8,%9}, {%0,%1,%2,%3};" \
        : "+f"((d)[0]), "+f"((d)[1]), "+f"((d)[2]), "+f"((d)[3]) \
        : "r"((a)[0]), "r"((a)[1]), "r"((a)[2]), "r"((a)[3]), \
          "r"(b0v), "r"(b1v))

// split two fp32 into packed bf16x2 hi and lo
__device__ __forceinline__ void split2(float a, float b, uint32_t& h, uint32_t& l) {
    __nv_bfloat162 hh = __floats2bfloat162_rn(a, b);
    float2 hf = __bfloat1622float2(hh);
    __nv_bfloat162 ll = __floats2bfloat162_rn(a - hf.x, b - hf.y);
    h = *(uint32_t*)&hh;
    l = *(uint32_t*)&ll;
}

// ---------------------------------------------------------------------------
// Split fp32 -> (bf16 hi, bf16 lo)
// ---------------------------------------------------------------------------
__global__ __launch_bounds__(256) void split_bf16(
    const float* __restrict__ src,
    __nv_bfloat16* __restrict__ hi, __nv_bfloat16* __restrict__ lo, int n4)
{
    int i = blockIdx.x * 256 + threadIdx.x;
    if (i >= n4) return;
    float4 v = ((const float4*)src)[i];
    uint32_t h0, l0, h1, l1;
    split2(v.x, v.y, h0, l0);
    split2(v.z, v.w, h1, l1);
    ((uint32_t*)hi)[2*i]     = h0;
    ((uint32_t*)hi)[2*i + 1] = h1;
    ((uint32_t*)lo)[2*i]     = l0;
    ((uint32_t*)lo)[2*i + 1] = l1;
}

// ---------------------------------------------------------------------------
// mma.sync bf16x3 GEMM, 128x128 tile, 8 warps, cp.async double buffer.
// SPLIT_OUT=0: fp32 out (+bias). SPLIT_OUT=1: bf16 hi/lo out (+bias).
// Combo loop hoisted OUTSIDE tile loops: consecutive HMMAs hit distinct
// accumulators (reuse distance 16) so the tensor pipe issues at throughput.
// ---------------------------------------------------------------------------
#define GOFF_AH 0u
#define GOFF_AL 10240u
#define GOFF_BH 20480u
#define GOFF_BL 29184u
#define GBUF    37888u
#define GEMM_SMEM_BYTES (2u * GBUF)

template<int SPLIT_OUT>
__global__ __launch_bounds__(256) void gemm_mma_bf16x3(
    const __nv_bfloat16* __restrict__ Ah, const __nv_bfloat16* __restrict__ Al,
    const __nv_bfloat16* __restrict__ Bh, const __nv_bfloat16* __restrict__ Bl,
    const float* __restrict__ bias, float* __restrict__ Cout,
    __nv_bfloat16* __restrict__ Ch, __nv_bfloat16* __restrict__ Cl,
    int M, int N, int K)
{
    extern __shared__ __align__(16) char smem[];
    const uint32_t sb = smem_to_u32(smem);
    const int tid  = threadIdx.x;
    const int warp = tid >> 5;
    const int lane = tid & 31;
    const int wm = warp & 1;
    const int wn = warp >> 1;
    const int row0 = blockIdx.y * 128;
    const int col0 = blockIdx.x * 128;

    const int ar = tid >> 2;
    const int ac = (tid & 3) * 8;
    const int bkr = tid >> 4;
    const int bnc = (tid & 15) * 8;

    const int nchunk = K >> 5;

    float acc[4][4][4];
    #pragma unroll
    for (int mt = 0; mt < 4; mt++)
        #pragma unroll
        for (int nt = 0; nt < 4; nt++)
            #pragma unroll
            for (int r = 0; r < 4; r++) acc[mt][nt][r] = 0.0f;

    {
        #pragma unroll
        for (int p = 0; p < 2; p++) {
            int r = ar + p * 64;
            CP_ASYNC16(sb + GOFF_AH + r*80 + ac*2, Ah + (size_t)(row0 + r) * K + ac);
            CP_ASYNC16(sb + GOFF_AL + r*80 + ac*2, Al + (size_t)(row0 + r) * K + ac);
            int kr = bkr + p * 16;
            CP_ASYNC16(sb + GOFF_BH + kr*272 + bnc*2, Bh + (size_t)kr * N + col0 + bnc);
            CP_ASYNC16(sb + GOFF_BL + kr*272 + bnc*2, Bl + (size_t)kr * N + col0 + bnc);
        }
        CP_ASYNC_COMMIT();
    }

    uint32_t buf = 0;
    for (int c = 0; c < nchunk; c++) {
        CP_ASYNC_WAIT0();
        __syncthreads();

        if (c + 1 < nchunk) {
            const uint32_t nb = sb + (buf ^ 1) * GBUF;
            const int kc0 = (c + 1) << 5;
            #pragma unroll
            for (int p = 0; p < 2; p++) {
                int r = ar + p * 64;
                CP_ASYNC16(nb + GOFF_AH + r*80 + ac*2, Ah + (size_t)(row0 + r) * K + kc0 + ac);
                CP_ASYNC16(nb + GOFF_AL + r*80 + ac*2, Al + (size_t)(row0 + r) * K + kc0 + ac);
                int kr = bkr + p * 16;
                CP_ASYNC16(nb + GOFF_BH + kr*272 + bnc*2, Bh + (size_t)(kc0 + kr) * N + col0 + bnc);
                CP_ASYNC16(nb + GOFF_BL + kr*272 + bnc*2, Bl + (size_t)(kc0 + kr) * N + col0 + bnc);
            }
            CP_ASYNC_COMMIT();
        }

        const uint32_t cb = sb + buf * GBUF;
        #pragma unroll
        for (int s = 0; s < 2; s++) {
            uint32_t a_h[4][4], a_l[4][4];
            const int arow_base = wm * 64 + (lane & 15);
            const int acol = (s * 16 + (lane >> 4) * 8) * 2;
            #pragma unroll
            for (int mt = 0; mt < 4; mt++) {
                uint32_t off = (uint32_t)((arow_base + mt * 16) * 80 + acol);
                LDMATRIX_X4(a_h[mt][0], a_h[mt][1], a_h[mt][2], a_h[mt][3], cb + GOFF_AH + off);
                LDMATRIX_X4(a_l[mt][0], a_l[mt][1], a_l[mt][2], a_l[mt][3], cb + GOFF_AL + off);
            }
            uint32_t b_h[2][4], b_l[2][4];
            const int g = lane >> 3;
            const int krow = s * 16 + (g & 1) * 8 + (lane & 7);
            #pragma unroll
            for (int ntp = 0; ntp < 2; ntp++) {
                const int ncol = wn * 32 + ntp * 16 + (g >> 1) * 8;
                uint32_t off = (uint32_t)(krow * 272 + ncol * 2);
                LDMATRIX_X4_T(b_h[ntp][0], b_h[ntp][1], b_h[ntp][2], b_h[ntp][3], cb + GOFF_BH + off);
                LDMATRIX_X4_T(b_l[ntp][0], b_l[ntp][1], b_l[ntp][2], b_l[ntp][3], cb + GOFF_BL + off);
            }
            // combo-outer: consecutive MMAs target distinct accumulators
            #pragma unroll
            for (int combo = 0; combo < 3; combo++) {
                #pragma unroll
                for (int mt = 0; mt < 4; mt++) {
                    const uint32_t* av = (combo == 2) ? a_l[mt] : a_h[mt];
                    #pragma unroll
                    for (int nt = 0; nt < 4; nt++) {
                        const uint32_t b0v = (combo == 1) ? b_l[nt >> 1][(nt & 1) * 2]
                                                          : b_h[nt >> 1][(nt & 1) * 2];
                        const uint32_t b1v = (combo == 1) ? b_l[nt >> 1][(nt & 1) * 2 + 1]
                                                          : b_h[nt >> 1][(nt & 1) * 2 + 1];
                        MMA_16816(acc[mt][nt], av, b0v, b1v);
                    }
                }
            }
        }
        buf ^= 1;
    }

    const int er = (lane >> 2);
    const int ec = (lane & 3) * 2;
    #pragma unroll
    for (int mt = 0; mt < 4; mt++) {
        #pragma unroll
        for (int nt = 0; nt < 4; nt++) {
            const int r  = row0 + wm * 64 + mt * 16 + er;
            const int cc = col0 + wn * 32 + nt * 8 + ec;
            float2 bv = *(const float2*)(bias + cc);
            float o0x = acc[mt][nt][0] + bv.x;
            float o0y = acc[mt][nt][1] + bv.y;
            float o1x = acc[mt][nt][2] + bv.x;
            float o1y = acc[mt][nt][3] + bv.y;
            if (SPLIT_OUT) {
                uint32_t h0, l0, h1, l1;
                split2(o0x, o0y, h0, l0);
                split2(o1x, o1y, h1, l1);
                *(uint32_t*)(Ch + (size_t)r * N + cc)       = h0;
                *(uint32_t*)(Cl + (size_t)r * N + cc)       = l0;
                *(uint32_t*)(Ch + (size_t)(r + 8) * N + cc) = h1;
                *(uint32_t*)(Cl + (size_t)(r + 8) * N + cc) = l1;
            } else {
                *(float2*)(Cout + (size_t)r * N + cc)       = make_float2(o0x, o0y);
                *(float2*)(Cout + (size_t)(r + 8) * N + cc) = make_float2(o1x, o1y);
            }
        }
    }
}

// ---------------------------------------------------------------------------
// Flash attention (causal) with mma.sync bf16x3; combo-outer MMA ordering.
// ---------------------------------------------------------------------------
#define BKV 64
#define AROW 144              // bytes per smem row
#define OKH 0u
#define OKL 9216u
#define OVH 18432u
#define OVL 27648u
#define ABUF 36864u
#define ATTN_SMEM_BYTES (2u * ABUF)

__global__ __launch_bounds__(256) void attn_mma(
    const __nv_bfloat16* __restrict__ qkvh, const __nv_bfloat16* __restrict__ qkvl,
    __nv_bfloat16* __restrict__ Yh, __nv_bfloat16* __restrict__ Yl)
{
    extern __shared__ __align__(16) char smem[];
    const uint32_t sb = smem_to_u32(smem);
    const int tid  = threadIdx.x;
    const int warp = tid >> 5;
    const int lane = tid & 31;

    const int qt = (int)(gridDim.x - 1 - blockIdx.x);   // heavy tiles first
    const int bh = blockIdx.y;
    const int b  = bh >> 4;
    const int h  = bh & 15;

    const size_t rowbase = (size_t)b * SEQ * C3 + h * HDIM;
    const __nv_bfloat16* qh_g = qkvh + rowbase;
    const __nv_bfloat16* ql_g = qkvl + rowbase;
    const __nv_bfloat16* kh_g = qkvh + rowbase + EMBD;
    const __nv_bfloat16* kl_g = qkvl + rowbase + EMBD;
    const __nv_bfloat16* vh_g = qkvh + rowbase + 2 * EMBD;
    const __nv_bfloat16* vl_g = qkvl + rowbase + 2 * EMBD;

    // ---- stage Q (128 rows x 64) hi/lo into smem, then to registers ----
    {
        #pragma unroll
        for (int it = 0; it < 4; it++) {
            int i = tid + it * 256;
            int row = i >> 3, ch = i & 7;
            const size_t go = (size_t)(qt * 128 + row) * C3 + ch * 8;
            CP_ASYNC16(sb + row * AROW + ch * 16,         qh_g + go);
            CP_ASYNC16(sb + 18432 + row * AROW + ch * 16, ql_g + go);
        }
        CP_ASYNC_COMMIT();
        CP_ASYNC_WAIT0();
        __syncthreads();
    }

    uint32_t aqh[4][4], aql[4][4];
    {
        const int arow = warp * 16 + (lane & 15);
        const int acby = (lane >> 4) * 16;
        #pragma unroll
        for (int kt4 = 0; kt4 < 4; kt4++) {
            uint32_t off = (uint32_t)(arow * AROW + kt4 * 32 + acby);
            LDMATRIX_X4(aqh[kt4][0], aqh[kt4][1], aqh[kt4][2], aqh[kt4][3], sb + off);
            LDMATRIX_X4(aql[kt4][0], aql[kt4][1], aql[kt4][2], aql[kt4][3], sb + 18432 + off);
        }
    }
    __syncthreads();   // done reading Q smem before K/V overwrite

    // ---- softmax state + O accumulators ----
    float m0 = -1e30f, m1 = -1e30f, l0 = 0.0f, l1 = 0.0f;
    float o[8][4];
    #pragma unroll
    for (int nt = 0; nt < 8; nt++)
        #pragma unroll
        for (int r = 0; r < 4; r++) o[nt][r] = 0.0f;

    const int nkv = 2 * qt + 2;

    // prefetch KV tiles 0 and 1
    #pragma unroll
    for (int pf = 0; pf < 2; pf++) {
        if (pf < nkv) {
            const uint32_t dst = sb + pf * ABUF;
            #pragma unroll
            for (int it = 0; it < 2; it++) {
                int i = tid + it * 256;
                int row = i >> 3, ch = i & 7;
                const size_t go = (size_t)(pf * BKV + row) * C3 + ch * 8;
                const uint32_t so = row * AROW + ch * 16;
                CP_ASYNC16(dst + OKH + so, kh_g + go);
                CP_ASYNC16(dst + OKL + so, kl_g + go);
                CP_ASYNC16(dst + OVH + so, vh_g + go);
                CP_ASYNC16(dst + OVL + so, vl_g + go);
            }
            CP_ASYNC_COMMIT();
        }
    }

    const float scale = 0.125f;  // 1/sqrt(64)

    for (int kt = 0; kt < nkv; kt++) {
        if (kt + 1 < nkv) { CP_ASYNC_WAIT1(); } else { CP_ASYNC_WAIT0(); }
        __syncthreads();

        const uint32_t cb = sb + (kt & 1) * ABUF;

        // ---- S = Qh*Kh^T + Qh*Kl^T + Ql*Kh^T  (m16 x n64, k=64) ----
        float s[8][4];
        #pragma unroll
        for (int nt = 0; nt < 8; nt++)
            #pragma unroll
            for (int r = 0; r < 4; r++) s[nt][r] = 0.0f;

        const int g = lane >> 3;
        #pragma unroll
        for (int kt4 = 0; kt4 < 4; kt4++) {
            uint32_t bkh[4][4], bkl[4][4];
            #pragma unroll
            for (int nt16 = 0; nt16 < 4; nt16++) {
                const int nrow = nt16 * 16 + (g & 1) * 8 + (lane & 7);
                const uint32_t off = (uint32_t)(nrow * AROW + kt4 * 32 + (g >> 1) * 16);
                LDMATRIX_X4(bkh[nt16][0], bkh[nt16][1], bkh[nt16][2], bkh[nt16][3], cb + OKH + off);
                LDMATRIX_X4(bkl[nt16][0], bkl[nt16][1], bkl[nt16][2], bkl[nt16][3], cb + OKL + off);
            }
            // combo-outer: 8 independent MMAs between same-acc reuses
            #pragma unroll
            for (int combo = 0; combo < 3; combo++) {
                const uint32_t* aq = (combo == 2) ? aql[kt4] : aqh[kt4];
                #pragma unroll
                for (int nt16 = 0; nt16 < 4; nt16++) {
                    #pragma unroll
                    for (int hv = 0; hv < 2; hv++) {
                        const int nt8 = nt16 * 2 + hv;
                        const uint32_t b0v = (combo == 1) ? bkl[nt16][hv]     : bkh[nt16][hv];
                        const uint32_t b1v = (combo == 1) ? bkl[nt16][2 + hv] : bkh[nt16][2 + hv];
                        MMA_16816(s[nt8], aq, b0v, b1v);
                    }
                }
            }
        }

        // ---- online softmax ----
        const bool need_mask = (kt >= 2 * qt);
        const int r0g = qt * 128 + warp * 16 + (lane >> 2);
        const int r1g = r0g + 8;
        float rmax0 = -1e30f, rmax1 = -1e30f;
        #pragma unroll
        for (int nt = 0; nt < 8; nt++) {
            #pragma unroll
            for (int j = 0; j < 2; j++) {
                const int kc = kt * BKV + nt * 8 + (lane & 3) * 2 + j;
                float v0 = s[nt][j] * scale;
                float v1 = s[nt][2 + j] * scale;
                if (need_mask) {
                    if (kc > r0g) v0 = -1e30f;
                    if (kc > r1g) v1 = -1e30f;
                }
                s[nt][j] = v0;     rmax0 = fmaxf(rmax0, v0);
                s[nt][2 + j] = v1; rmax1 = fmaxf(rmax1, v1);
            }
        }
        rmax0 = fmaxf(rmax0, __shfl_xor_sync(0xffffffffu, rmax0, 1));
        rmax0 = fmaxf(rmax0, __shfl_xor_sync(0xffffffffu, rmax0, 2));
        rmax1 = fmaxf(rmax1, __shfl_xor_sync(0xffffffffu, rmax1, 1));
        rmax1 = fmaxf(rmax1, __shfl_xor_sync(0xffffffffu, rmax1, 2));

        const float mn0 = fmaxf(m0, rmax0);
        const float mn1 = fmaxf(m1, rmax1);
        const float alpha0 = __expf(m0 - mn0);
        const float alpha1 = __expf(m1 - mn1);
        m0 = mn0; m1 = mn1;

        float ps0 = 0.0f, ps1 = 0.0f;
        #pragma unroll
        for (int nt = 0; nt < 8; nt++) {
            #pragma unroll
            for (int j = 0; j < 2; j++) {
                float p0 = __expf(s[nt][j] - mn0);
                float p1 = __expf(s[nt][2 + j] - mn1);
                s[nt][j] = p0;     ps0 += p0;
                s[nt][2 + j] = p1; ps1 += p1;
            }
        }
        ps0 += __shfl_xor_sync(0xffffffffu, ps0, 1);
        ps0 += __shfl_xor_sync(0xffffffffu, ps0, 2);
        ps1 += __shfl_xor_sync(0xffffffffu, ps1, 1);
        ps1 += __shfl_xor_sync(0xffffffffu, ps1, 2);
        l0 = l0 * alpha0 + ps0;
        l1 = l1 * alpha1 + ps1;

        #pragma unroll
        for (int nt = 0; nt < 8; nt++) {
            o[nt][0] *= alpha0; o[nt][1] *= alpha0;
            o[nt][2] *= alpha1; o[nt][3] *= alpha1;
        }

        // ---- pack P -> bf16 hi/lo A-fragments (C-frag == A-frag mapping) ----
        uint32_t aph[4][4], apl[4][4];
        #pragma unroll
        for (int pt = 0; pt < 4; pt++) {
            split2(s[2*pt][0],   s[2*pt][1],   aph[pt][0], apl[pt][0]);
            split2(s[2*pt][2],   s[2*pt][3],   aph[pt][1], apl[pt][1]);
            split2(s[2*pt+1][0], s[2*pt+1][1], aph[pt][2], apl[pt][2]);
            split2(s[2*pt+1][2], s[2*pt+1][3], aph[pt][3], apl[pt][3]);
        }

        // ---- O += P @ V ----
        #pragma unroll
        for (int pt = 0; pt < 4; pt++) {
            uint32_t bvh[4][4], bvl[4][4];
            #pragma unroll
            for (int nt16 = 0; nt16 < 4; nt16++) {
                const int krow = pt * 16 + (g & 1) * 8 + (lane & 7);
                const uint32_t off = (uint32_t)(krow * AROW + nt16 * 32 + (g >> 1) * 16);
                LDMATRIX_X4_T(bvh[nt16][0], bvh[nt16][1], bvh[nt16][2], bvh[nt16][3], cb + OVH + off);
                LDMATRIX_X4_T(bvl[nt16][0], bvl[nt16][1], bvl[nt16][2], bvl[nt16][3], cb + OVL + off);
            }
            // combo-outer
            #pragma unroll
            for (int combo = 0; combo < 3; combo++) {
                const uint32_t* ap = (combo == 2) ? apl[pt] : aph[pt];
                #pragma unroll
                for (int nt16 = 0; nt16 < 4; nt16++) {
                    #pragma unroll
                    for (int hv = 0; hv < 2; hv++) {
                        const int nt8 = nt16 * 2 + hv;
                        const uint32_t b0v = (combo == 1) ? bvl[nt16][hv * 2]     : bvh[nt16][hv * 2];
                        const uint32_t b1v = (combo == 1) ? bvl[nt16][hv * 2 + 1] : bvh[nt16][hv * 2 + 1];
                        MMA_16816(o[nt8], ap, b0v, b1v);
                    }
                }
            }
        }

        __syncthreads();   // all warps done with this buffer

        if (kt + 2 < nkv) {
            const uint32_t dst = sb + (kt & 1) * ABUF;
            #pragma unroll
            for (int it = 0; it < 2; it++) {
                int i = tid + it * 256;
                int row = i >> 3, ch = i & 7;
                const size_t go = (size_t)((kt + 2) * BKV + row) * C3 + ch * 8;
                const uint32_t so = row * AROW + ch * 16;
                CP_ASYNC16(dst + OKH + so, kh_g + go);
                CP_ASYNC16(dst + OKL + so, kl_g + go);
                CP_ASYNC16(dst + OVH + so, vh_g + go);
                CP_ASYNC16(dst + OVL + so, vl_g + go);
            }
            CP_ASYNC_COMMIT();
        }
    }

    // ---- epilogue: normalize, split to bf16 hi/lo, store ----
    const float inv0 = 1.0f / l0;
    const float inv1 = 1.0f / l1;
    const int tr0 = qt * 128 + warp * 16 + (lane >> 2);
    const size_t ybase = (size_t)b * SEQ * EMBD + h * HDIM;
    #pragma unroll
    for (int nt = 0; nt < 8; nt++) {
        const int col = nt * 8 + (lane & 3) * 2;
        uint32_t h0, lo0, h1, lo1;
        split2(o[nt][0] * inv0, o[nt][1] * inv0, h0, lo0);
        split2(o[nt][2] * inv1, o[nt][3] * inv1, h1, lo1);
        *(uint32_t*)(Yh + ybase + (size_t)tr0 * EMBD + col)       = h0;
        *(uint32_t*)(Yl + ybase + (size_t)tr0 * EMBD + col)       = lo0;
        *(uint32_t*)(Yh + ybase + (size_t)(tr0 + 8) * EMBD + col) = h1;
        *(uint32_t*)(Yl + ybase + (size_t)(tr0 + 8) * EMBD + col) = lo1;
    }
}

// ---------------------------------------------------------------------------
extern "C" void kernel_launch(void* const* d_in, const int* in_sizes, int n_in,
                              void* d_out, int out_size)
{
    const float* x      = (const float*)d_in[0];
    const float* W_attn = (const float*)d_in[1];
    const float* b_attn = (const float*)d_in[2];
    const float* W_proj = (const float*)d_in[3];
    const float* b_proj = (const float*)d_in[4];
    float* out = (float*)d_out;

    __nv_bfloat16 *qkvh, *qkvl, *xh, *xl, *wah, *wal, *wph, *wpl, *yh, *yl;
    cudaGetSymbolAddress((void**)&qkvh, g_qkvh);
    cudaGetSymbolAddress((void**)&qkvl, g_qkvl);
    cudaGetSymbolAddress((void**)&xh,  g_xh);
    cudaGetSymbolAddress((void**)&xl,  g_xl);
    cudaGetSymbolAddress((void**)&wah, g_wah);
    cudaGetSymbolAddress((void**)&wal, g_wal);
    cudaGetSymbolAddress((void**)&wph, g_wph);
    cudaGetSymbolAddress((void**)&wpl, g_wpl);
    cudaGetSymbolAddress((void**)&yh,  g_yh);
    cudaGetSymbolAddress((void**)&yl,  g_yl);

    cudaFuncSetAttribute(gemm_mma_bf16x3<0>,
                         cudaFuncAttributeMaxDynamicSharedMemorySize, GEMM_SMEM_BYTES);
    cudaFuncSetAttribute(gemm_mma_bf16x3<1>,
                         cudaFuncAttributeMaxDynamicSharedMemorySize, GEMM_SMEM_BYTES);
    cudaFuncSetAttribute(attn_mma,
                         cudaFuncAttributeMaxDynamicSharedMemorySize, ATTN_SMEM_BYTES);

    // 0) split inputs
    {
        int n4 = BT * EMBD / 4;
        split_bf16<<<(n4 + 255) / 256, 256>>>(x, xh, xl, n4);
        n4 = EMBD * C3 / 4;
        split_bf16<<<(n4 + 255) / 256, 256>>>(W_attn, wah, wal, n4);
        n4 = EMBD * EMBD / 4;
        split_bf16<<<(n4 + 255) / 256, 256>>>(W_proj, wph, wpl, n4);
    }
    // 1) QKV GEMM -> bf16 hi/lo qkv (bias fused, split fused)
    {
        dim3 grid(C3 / 128, BT / 128);
        gemm_mma_bf16x3<1><<<grid, 256, GEMM_SMEM_BYTES>>>(
            xh, xl, wah, wal, b_attn, nullptr, qkvh, qkvl, BT, C3, EMBD);
    }
    // 2) causal flash attention (mma.sync bf16x3) -> bf16 hi/lo y
    {
        dim3 grid(SEQ / 128, BATCH * NHEAD);
        attn_mma<<<grid, 256, ATTN_SMEM_BYTES>>>(qkvh, qkvl, yh, yl);
    }
    // 3) proj GEMM -> fp32 out
    {
        dim3 grid(EMBD / 128, BT / 128);
        gemm_mma_bf16x3<0><<<grid, 256, GEMM_SMEM_BYTES>>>(
            yh, yl, wph, wpl, b_proj, out, nullptr, nullptr, BT, EMBD, EMBD);
    }
}

// round 11
// speedup vs baseline: 2.7967x; 1.0052x over previous
#include <cuda_runtime.h>
#include <cuda_bf16.h>
#include <cstdint>

// ---------------------------------------------------------------------------
// Problem constants
// ---------------------------------------------------------------------------
#define BATCH 4
#define SEQ   2048
#define EMBD  1024
#define NHEAD 16
#define HDIM  64
#define BT    (BATCH*SEQ)        // 8192
#define C3    (3*EMBD)           // 3072

// ---------------------------------------------------------------------------
// Scratch (device globals — no allocation allowed)
// ---------------------------------------------------------------------------
__device__ __nv_bfloat16 g_qkvh[(size_t)BT * C3];
__device__ __nv_bfloat16 g_qkvl[(size_t)BT * C3];
__device__ __nv_bfloat16 g_xh[(size_t)BT * EMBD];
__device__ __nv_bfloat16 g_xl[(size_t)BT * EMBD];
__device__ __nv_bfloat16 g_wah[(size_t)EMBD * C3];
__device__ __nv_bfloat16 g_wal[(size_t)EMBD * C3];
__device__ __nv_bfloat16 g_wph[(size_t)EMBD * EMBD];
__device__ __nv_bfloat16 g_wpl[(size_t)EMBD * EMBD];
__device__ __nv_bfloat16 g_yh[(size_t)BT * EMBD];
__device__ __nv_bfloat16 g_yl[(size_t)BT * EMBD];

// ---------------------------------------------------------------------------
// PTX helpers (sm_80+ portable: mma.sync / ldmatrix / cp.async)
// ---------------------------------------------------------------------------
__device__ __forceinline__ uint32_t smem_to_u32(const void* smem_ptr) {
    uint32_t addr;
    asm("{ .reg .u64 tmp; cvta.to.shared.u64 tmp, %1; cvt.u32.u64 %0, tmp; }"
        : "=r"(addr) : "l"(smem_ptr));
    return addr;
}

#define CP_ASYNC16(saddr, gptr) \
    asm volatile("cp.async.cg.shared.global [%0], [%1], 16;" \
        :: "r"(saddr), "l"(gptr) : "memory")
#define CP_ASYNC_COMMIT() asm volatile("cp.async.commit_group;" ::: "memory")
#define CP_ASYNC_WAIT0()  asm volatile("cp.async.wait_group 0;" ::: "memory")
#define CP_ASYNC_WAIT1()  asm volatile("cp.async.wait_group 1;" ::: "memory")

#define LDMATRIX_X4(r0,r1,r2,r3, addr) \
    asm volatile("ldmatrix.sync.aligned.m8n8.x4.shared.b16 {%0,%1,%2,%3}, [%4];" \
        : "=r"(r0), "=r"(r1), "=r"(r2), "=r"(r3) : "r"(addr))

#define LDMATRIX_X4_T(r0,r1,r2,r3, addr) \
    asm volatile("ldmatrix.sync.aligned.m8n8.x4.trans.shared.b16 {%0,%1,%2,%3}, [%4];" \
        : "=r"(r0), "=r"(r1), "=r"(r2), "=r"(r3) : "r"(addr))

#define MMA_16816(d, a, b0v, b1v) \
    asm volatile( \
        "mma.sync.aligned.m16n8k16.row.col.f32.bf16.bf16.f32 " \
        "{%0,%1,%2,%3}, {%4,%5,%6,%7}, {%8,%9}, {%0,%1,%2,%3};" \
        : "+f"((d)[0]), "+f"((d)[1]), "+f"((d)[2]), "+f"((d)[3]) \
        : "r"((a)[0]), "r"((a)[1]), "r"((a)[2]), "r"((a)[3]), \
          "r"(b0v), "r"(b1v))

// split two fp32 into packed bf16x2 hi and lo
__device__ __forceinline__ void split2(float a, float b, uint32_t& h, uint32_t& l) {
    __nv_bfloat162 hh = __floats2bfloat162_rn(a, b);
    float2 hf = __bfloat1622float2(hh);
    __nv_bfloat162 ll = __floats2bfloat162_rn(a - hf.x, b - hf.y);
    h = *(uint32_t*)&hh;
    l = *(uint32_t*)&ll;
}

// ---------------------------------------------------------------------------
// Split fp32 -> (bf16 hi, bf16 lo)
// ---------------------------------------------------------------------------
__global__ __launch_bounds__(256) void split_bf16(
    const float* __restrict__ src,
    __nv_bfloat16* __restrict__ hi, __nv_bfloat16* __restrict__ lo, int n4)
{
    int i = blockIdx.x * 256 + threadIdx.x;
    if (i >= n4) return;
    float4 v = ((const float4*)src)[i];
    uint32_t h0, l0, h1, l1;
    split2(v.x, v.y, h0, l0);
    split2(v.z, v.w, h1, l1);
    ((uint32_t*)hi)[2*i]     = h0;
    ((uint32_t*)hi)[2*i + 1] = h1;
    ((uint32_t*)lo)[2*i]     = l0;
    ((uint32_t*)lo)[2*i + 1] = l1;
}

// ---------------------------------------------------------------------------
// mma.sync bf16x3 GEMM, 128x128 CTA tile, 4 warps (warp tile 64x64),
// cp.async double buffer. Bigger warp tile: A fragments reused over 8 n-tiles,
// B over 4 m-tiles -> 128 ldmatrix.x4 per CTA-chunk (was 192), longer
// uninterrupted HMMA runs per warp.
// SPLIT_OUT=0: fp32 out (+bias). SPLIT_OUT=1: bf16 hi/lo out (+bias).
// ---------------------------------------------------------------------------
#define GOFF_AH 0u
#define GOFF_AL 10240u
#define GOFF_BH 20480u
#define GOFF_BL 29184u
#define GBUF    37888u
#define GEMM_SMEM_BYTES (2u * GBUF)

template<int SPLIT_OUT>
__global__ __launch_bounds__(128) void gemm_mma_bf16x3(
    const __nv_bfloat16* __restrict__ Ah, const __nv_bfloat16* __restrict__ Al,
    const __nv_bfloat16* __restrict__ Bh, const __nv_bfloat16* __restrict__ Bl,
    const float* __restrict__ bias, float* __restrict__ Cout,
    __nv_bfloat16* __restrict__ Ch, __nv_bfloat16* __restrict__ Cl,
    int M, int N, int K)
{
    extern __shared__ __align__(16) char smem[];
    const uint32_t sb = smem_to_u32(smem);
    const int tid  = threadIdx.x;
    const int warp = tid >> 5;
    const int lane = tid & 31;
    const int wm = warp >> 1;     // 0..1 -> m offset *64
    const int wn = warp & 1;      // 0..1 -> n offset *64
    const int row0 = blockIdx.y * 128;
    const int col0 = blockIdx.x * 128;

    // global load mapping (128 threads): A: 32 rows/pass x 64B; B: 8 k-rows/pass x 256B
    const int ar = tid >> 2;             // 0..31
    const int ac = (tid & 3) * 8;        // elem offset in k
    const int bkr = tid >> 4;            // 0..7
    const int bnc = (tid & 15) * 8;      // elem offset in n

    const int nchunk = K >> 5;

    float acc[4][8][4];
    #pragma unroll
    for (int mt = 0; mt < 4; mt++)
        #pragma unroll
        for (int nt = 0; nt < 8; nt++)
            #pragma unroll
            for (int r = 0; r < 4; r++) acc[mt][nt][r] = 0.0f;

    {
        #pragma unroll
        for (int p = 0; p < 4; p++) {
            int r = ar + p * 32;
            CP_ASYNC16(sb + GOFF_AH + r*80 + ac*2, Ah + (size_t)(row0 + r) * K + ac);
            CP_ASYNC16(sb + GOFF_AL + r*80 + ac*2, Al + (size_t)(row0 + r) * K + ac);
            int kr = bkr + p * 8;
            CP_ASYNC16(sb + GOFF_BH + kr*272 + bnc*2, Bh + (size_t)kr * N + col0 + bnc);
            CP_ASYNC16(sb + GOFF_BL + kr*272 + bnc*2, Bl + (size_t)kr * N + col0 + bnc);
        }
        CP_ASYNC_COMMIT();
    }

    uint32_t buf = 0;
    for (int c = 0; c < nchunk; c++) {
        CP_ASYNC_WAIT0();
        __syncthreads();

        if (c + 1 < nchunk) {
            const uint32_t nb = sb + (buf ^ 1) * GBUF;
            const int kc0 = (c + 1) << 5;
            #pragma unroll
            for (int p = 0; p < 4; p++) {
                int r = ar + p * 32;
                CP_ASYNC16(nb + GOFF_AH + r*80 + ac*2, Ah + (size_t)(row0 + r) * K + kc0 + ac);
                CP_ASYNC16(nb + GOFF_AL + r*80 + ac*2, Al + (size_t)(row0 + r) * K + kc0 + ac);
                int kr = bkr + p * 8;
                CP_ASYNC16(nb + GOFF_BH + kr*272 + bnc*2, Bh + (size_t)(kc0 + kr) * N + col0 + bnc);
                CP_ASYNC16(nb + GOFF_BL + kr*272 + bnc*2, Bl + (size_t)(kc0 + kr) * N + col0 + bnc);
            }
            CP_ASYNC_COMMIT();
        }

        const uint32_t cb = sb + buf * GBUF;
        #pragma unroll
        for (int s = 0; s < 2; s++) {
            uint32_t a_h[4][4], a_l[4][4];
            const int arow_base = wm * 64 + (lane & 15);
            const int acol = (s * 16 + (lane >> 4) * 8) * 2;
            #pragma unroll
            for (int mt = 0; mt < 4; mt++) {
                uint32_t off = (uint32_t)((arow_base + mt * 16) * 80 + acol);
                LDMATRIX_X4(a_h[mt][0], a_h[mt][1], a_h[mt][2], a_h[mt][3], cb + GOFF_AH + off);
                LDMATRIX_X4(a_l[mt][0], a_l[mt][1], a_l[mt][2], a_l[mt][3], cb + GOFF_AL + off);
            }
            uint32_t b_h[4][4], b_l[4][4];
            const int g = lane >> 3;
            const int krow = s * 16 + (g & 1) * 8 + (lane & 7);
            #pragma unroll
            for (int ntp = 0; ntp < 4; ntp++) {
                const int ncol = wn * 64 + ntp * 16 + (g >> 1) * 8;
                uint32_t off = (uint32_t)(krow * 272 + ncol * 2);
                LDMATRIX_X4_T(b_h[ntp][0], b_h[ntp][1], b_h[ntp][2], b_h[ntp][3], cb + GOFF_BH + off);
                LDMATRIX_X4_T(b_l[ntp][0], b_l[ntp][1], b_l[ntp][2], b_l[ntp][3], cb + GOFF_BL + off);
            }
            // combo-outer: consecutive MMAs target distinct accumulators
            #pragma unroll
            for (int combo = 0; combo < 3; combo++) {
                #pragma unroll
                for (int mt = 0; mt < 4; mt++) {
                    const uint32_t* av = (combo == 2) ? a_l[mt] : a_h[mt];
                    #pragma unroll
                    for (int nt = 0; nt < 8; nt++) {
                        const uint32_t b0v = (combo == 1) ? b_l[nt >> 1][(nt & 1) * 2]
                                                          : b_h[nt >> 1][(nt & 1) * 2];
                        const uint32_t b1v = (combo == 1) ? b_l[nt >> 1][(nt & 1) * 2 + 1]
                                                          : b_h[nt >> 1][(nt & 1) * 2 + 1];
                        MMA_16816(acc[mt][nt], av, b0v, b1v);
                    }
                }
            }
        }
        buf ^= 1;
    }

    const int er = (lane >> 2);
    const int ec = (lane & 3) * 2;
    #pragma unroll
    for (int mt = 0; mt < 4; mt++) {
        #pragma unroll
        for (int nt = 0; nt < 8; nt++) {
            const int r  = row0 + wm * 64 + mt * 16 + er;
            const int cc = col0 + wn * 64 + nt * 8 + ec;
            float2 bv = *(const float2*)(bias + cc);
            float o0x = acc[mt][nt][0] + bv.x;
            float o0y = acc[mt][nt][1] + bv.y;
            float o1x = acc[mt][nt][2] + bv.x;
            float o1y = acc[mt][nt][3] + bv.y;
            if (SPLIT_OUT) {
                uint32_t h0, l0, h1, l1;
                split2(o0x, o0y, h0, l0);
                split2(o1x, o1y, h1, l1);
                *(uint32_t*)(Ch + (size_t)r * N + cc)       = h0;
                *(uint32_t*)(Cl + (size_t)r * N + cc)       = l0;
                *(uint32_t*)(Ch + (size_t)(r + 8) * N + cc) = h1;
                *(uint32_t*)(Cl + (size_t)(r + 8) * N + cc) = l1;
            } else {
                *(float2*)(Cout + (size_t)r * N + cc)       = make_float2(o0x, o0y);
                *(float2*)(Cout + (size_t)(r + 8) * N + cc) = make_float2(o1x, o1y);
            }
        }
    }
}

// ---------------------------------------------------------------------------
// Flash attention (causal) with mma.sync bf16x3 — unchanged from R8 passing.
// ---------------------------------------------------------------------------
#define BKV 64
#define AROW 144              // bytes per smem row
#define OKH 0u
#define OKL 9216u
#define OVH 18432u
#define OVL 27648u
#define ABUF 36864u
#define ATTN_SMEM_BYTES (2u * ABUF)

__global__ __launch_bounds__(256) void attn_mma(
    const __nv_bfloat16* __restrict__ qkvh, const __nv_bfloat16* __restrict__ qkvl,
    __nv_bfloat16* __restrict__ Yh, __nv_bfloat16* __restrict__ Yl)
{
    extern __shared__ __align__(16) char smem[];
    const uint32_t sb = smem_to_u32(smem);
    const int tid  = threadIdx.x;
    const int warp = tid >> 5;
    const int lane = tid & 31;

    const int qt = (int)(gridDim.x - 1 - blockIdx.x);   // heavy tiles first
    const int bh = blockIdx.y;
    const int b  = bh >> 4;
    const int h  = bh & 15;

    const size_t rowbase = (size_t)b * SEQ * C3 + h * HDIM;
    const __nv_bfloat16* qh_g = qkvh + rowbase;
    const __nv_bfloat16* ql_g = qkvl + rowbase;
    const __nv_bfloat16* kh_g = qkvh + rowbase + EMBD;
    const __nv_bfloat16* kl_g = qkvl + rowbase + EMBD;
    const __nv_bfloat16* vh_g = qkvh + rowbase + 2 * EMBD;
    const __nv_bfloat16* vl_g = qkvl + rowbase + 2 * EMBD;

    // ---- stage Q (128 rows x 64) hi/lo into smem, then to registers ----
    {
        #pragma unroll
        for (int it = 0; it < 4; it++) {
            int i = tid + it * 256;
            int row = i >> 3, ch = i & 7;
            const size_t go = (size_t)(qt * 128 + row) * C3 + ch * 8;
            CP_ASYNC16(sb + row * AROW + ch * 16,         qh_g + go);
            CP_ASYNC16(sb + 18432 + row * AROW + ch * 16, ql_g + go);
        }
        CP_ASYNC_COMMIT();
        CP_ASYNC_WAIT0();
        __syncthreads();
    }

    uint32_t aqh[4][4], aql[4][4];
    {
        const int arow = warp * 16 + (lane & 15);
        const int acby = (lane >> 4) * 16;
        #pragma unroll
        for (int kt4 = 0; kt4 < 4; kt4++) {
            uint32_t off = (uint32_t)(arow * AROW + kt4 * 32 + acby);
            LDMATRIX_X4(aqh[kt4][0], aqh[kt4][1], aqh[kt4][2], aqh[kt4][3], sb + off);
            LDMATRIX_X4(aql[kt4][0], aql[kt4][1], aql[kt4][2], aql[kt4][3], sb + 18432 + off);
        }
    }
    __syncthreads();   // done reading Q smem before K/V overwrite

    // ---- softmax state + O accumulators ----
    float m0 = -1e30f, m1 = -1e30f, l0 = 0.0f, l1 = 0.0f;
    float o[8][4];
    #pragma unroll
    for (int nt = 0; nt < 8; nt++)
        #pragma unroll
        for (int r = 0; r < 4; r++) o[nt][r] = 0.0f;

    const int nkv = 2 * qt + 2;

    // prefetch KV tiles 0 and 1
    #pragma unroll
    for (int pf = 0; pf < 2; pf++) {
        if (pf < nkv) {
            const uint32_t dst = sb + pf * ABUF;
            #pragma unroll
            for (int it = 0; it < 2; it++) {
                int i = tid + it * 256;
                int row = i >> 3, ch = i & 7;
                const size_t go = (size_t)(pf * BKV + row) * C3 + ch * 8;
                const uint32_t so = row * AROW + ch * 16;
                CP_ASYNC16(dst + OKH + so, kh_g + go);
                CP_ASYNC16(dst + OKL + so, kl_g + go);
                CP_ASYNC16(dst + OVH + so, vh_g + go);
                CP_ASYNC16(dst + OVL + so, vl_g + go);
            }
            CP_ASYNC_COMMIT();
        }
    }

    const float scale = 0.125f;  // 1/sqrt(64)

    for (int kt = 0; kt < nkv; kt++) {
        if (kt + 1 < nkv) { CP_ASYNC_WAIT1(); } else { CP_ASYNC_WAIT0(); }
        __syncthreads();

        const uint32_t cb = sb + (kt & 1) * ABUF;

        // ---- S = Qh*Kh^T + Qh*Kl^T + Ql*Kh^T  (m16 x n64, k=64) ----
        float s[8][4];
        #pragma unroll
        for (int nt = 0; nt < 8; nt++)
            #pragma unroll
            for (int r = 0; r < 4; r++) s[nt][r] = 0.0f;

        const int g = lane >> 3;
        #pragma unroll
        for (int kt4 = 0; kt4 < 4; kt4++) {
            uint32_t bkh[4][4], bkl[4][4];
            #pragma unroll
            for (int nt16 = 0; nt16 < 4; nt16++) {
                const int nrow = nt16 * 16 + (g & 1) * 8 + (lane & 7);
                const uint32_t off = (uint32_t)(nrow * AROW + kt4 * 32 + (g >> 1) * 16);
                LDMATRIX_X4(bkh[nt16][0], bkh[nt16][1], bkh[nt16][2], bkh[nt16][3], cb + OKH + off);
                LDMATRIX_X4(bkl[nt16][0], bkl[nt16][1], bkl[nt16][2], bkl[nt16][3], cb + OKL + off);
            }
            // combo-outer: 8 independent MMAs between same-acc reuses
            #pragma unroll
            for (int combo = 0; combo < 3; combo++) {
                const uint32_t* aq = (combo == 2) ? aql[kt4] : aqh[kt4];
                #pragma unroll
                for (int nt16 = 0; nt16 < 4; nt16++) {
                    #pragma unroll
                    for (int hv = 0; hv < 2; hv++) {
                        const int nt8 = nt16 * 2 + hv;
                        const uint32_t b0v = (combo == 1) ? bkl[nt16][hv]     : bkh[nt16][hv];
                        const uint32_t b1v = (combo == 1) ? bkl[nt16][2 + hv] : bkh[nt16][2 + hv];
                        MMA_16816(s[nt8], aq, b0v, b1v);
                    }
                }
            }
        }

        // ---- online softmax ----
        const bool need_mask = (kt >= 2 * qt);
        const int r0g = qt * 128 + warp * 16 + (lane >> 2);
        const int r1g = r0g + 8;
        float rmax0 = -1e30f, rmax1 = -1e30f;
        #pragma unroll
        for (int nt = 0; nt < 8; nt++) {
            #pragma unroll
            for (int j = 0; j < 2; j++) {
                const int kc = kt * BKV + nt * 8 + (lane & 3) * 2 + j;
                float v0 = s[nt][j] * scale;
                float v1 = s[nt][2 + j] * scale;
                if (need_mask) {
                    if (kc > r0g) v0 = -1e30f;
                    if (kc > r1g) v1 = -1e30f;
                }
                s[nt][j] = v0;     rmax0 = fmaxf(rmax0, v0);
                s[nt][2 + j] = v1; rmax1 = fmaxf(rmax1, v1);
            }
        }
        rmax0 = fmaxf(rmax0, __shfl_xor_sync(0xffffffffu, rmax0, 1));
        rmax0 = fmaxf(rmax0, __shfl_xor_sync(0xffffffffu, rmax0, 2));
        rmax1 = fmaxf(rmax1, __shfl_xor_sync(0xffffffffu, rmax1, 1));
        rmax1 = fmaxf(rmax1, __shfl_xor_sync(0xffffffffu, rmax1, 2));

        const float mn0 = fmaxf(m0, rmax0);
        const float mn1 = fmaxf(m1, rmax1);
        const float alpha0 = __expf(m0 - mn0);
        const float alpha1 = __expf(m1 - mn1);
        m0 = mn0; m1 = mn1;

        float ps0 = 0.0f, ps1 = 0.0f;
        #pragma unroll
        for (int nt = 0; nt < 8; nt++) {
            #pragma unroll
            for (int j = 0; j < 2; j++) {
                float p0 = __expf(s[nt][j] - mn0);
                float p1 = __expf(s[nt][2 + j] - mn1);
                s[nt][j] = p0;     ps0 += p0;
                s[nt][2 + j] = p1; ps1 += p1;
            }
        }
        ps0 += __shfl_xor_sync(0xffffffffu, ps0, 1);
        ps0 += __shfl_xor_sync(0xffffffffu, ps0, 2);
        ps1 += __shfl_xor_sync(0xffffffffu, ps1, 1);
        ps1 += __shfl_xor_sync(0xffffffffu, ps1, 2);
        l0 = l0 * alpha0 + ps0;
        l1 = l1 * alpha1 + ps1;

        #pragma unroll
        for (int nt = 0; nt < 8; nt++) {
            o[nt][0] *= alpha0; o[nt][1] *= alpha0;
            o[nt][2] *= alpha1; o[nt][3] *= alpha1;
        }

        // ---- pack P -> bf16 hi/lo A-fragments (C-frag == A-frag mapping) ----
        uint32_t aph[4][4], apl[4][4];
        #pragma unroll
        for (int pt = 0; pt < 4; pt++) {
            split2(s[2*pt][0],   s[2*pt][1],   aph[pt][0], apl[pt][0]);
            split2(s[2*pt][2],   s[2*pt][3],   aph[pt][1], apl[pt][1]);
            split2(s[2*pt+1][0], s[2*pt+1][1], aph[pt][2], apl[pt][2]);
            split2(s[2*pt+1][2], s[2*pt+1][3], aph[pt][3], apl[pt][3]);
        }

        // ---- O += P @ V ----
        #pragma unroll
        for (int pt = 0; pt < 4; pt++) {
            uint32_t bvh[4][4], bvl[4][4];
            #pragma unroll
            for (int nt16 = 0; nt16 < 4; nt16++) {
                const int krow = pt * 16 + (g & 1) * 8 + (lane & 7);
                const uint32_t off = (uint32_t)(krow * AROW + nt16 * 32 + (g >> 1) * 16);
                LDMATRIX_X4_T(bvh[nt16][0], bvh[nt16][1], bvh[nt16][2], bvh[nt16][3], cb + OVH + off);
                LDMATRIX_X4_T(bvl[nt16][0], bvl[nt16][1], bvl[nt16][2], bvl[nt16][3], cb + OVL + off);
            }
            // combo-outer
            #pragma unroll
            for (int combo = 0; combo < 3; combo++) {
                const uint32_t* ap = (combo == 2) ? apl[pt] : aph[pt];
                #pragma unroll
                for (int nt16 = 0; nt16 < 4; nt16++) {
                    #pragma unroll
                    for (int hv = 0; hv < 2; hv++) {
                        const int nt8 = nt16 * 2 + hv;
                        const uint32_t b0v = (combo == 1) ? bvl[nt16][hv * 2]     : bvh[nt16][hv * 2];
                        const uint32_t b1v = (combo == 1) ? bvl[nt16][hv * 2 + 1] : bvh[nt16][hv * 2 + 1];
                        MMA_16816(o[nt8], ap, b0v, b1v);
                    }
                }
            }
        }

        __syncthreads();   // all warps done with this buffer

        if (kt + 2 < nkv) {
            const uint32_t dst = sb + (kt & 1) * ABUF;
            #pragma unroll
            for (int it = 0; it < 2; it++) {
                int i = tid + it * 256;
                int row = i >> 3, ch = i & 7;
                const size_t go = (size_t)((kt + 2) * BKV + row) * C3 + ch * 8;
                const uint32_t so = row * AROW + ch * 16;
                CP_ASYNC16(dst + OKH + so, kh_g + go);
                CP_ASYNC16(dst + OKL + so, kl_g + go);
                CP_ASYNC16(dst + OVH + so, vh_g + go);
                CP_ASYNC16(dst + OVL + so, vl_g + go);
            }
            CP_ASYNC_COMMIT();
        }
    }

    // ---- epilogue: normalize, split to bf16 hi/lo, store ----
    const float inv0 = 1.0f / l0;
    const float inv1 = 1.0f / l1;
    const int tr0 = qt * 128 + warp * 16 + (lane >> 2);
    const size_t ybase = (size_t)b * SEQ * EMBD + h * HDIM;
    #pragma unroll
    for (int nt = 0; nt < 8; nt++) {
        const int col = nt * 8 + (lane & 3) * 2;
        uint32_t h0, lo0, h1, lo1;
        split2(o[nt][0] * inv0, o[nt][1] * inv0, h0, lo0);
        split2(o[nt][2] * inv1, o[nt][3] * inv1, h1, lo1);
        *(uint32_t*)(Yh + ybase + (size_t)tr0 * EMBD + col)       = h0;
        *(uint32_t*)(Yl + ybase + (size_t)tr0 * EMBD + col)       = lo0;
        *(uint32_t*)(Yh + ybase + (size_t)(tr0 + 8) * EMBD + col) = h1;
        *(uint32_t*)(Yl + ybase + (size_t)(tr0 + 8) * EMBD + col) = lo1;
    }
}

// ---------------------------------------------------------------------------
extern "C" void kernel_launch(void* const* d_in, const int* in_sizes, int n_in,
                              void* d_out, int out_size)
{
    const float* x      = (const float*)d_in[0];
    const float* W_attn = (const float*)d_in[1];
    const float* b_attn = (const float*)d_in[2];
    const float* W_proj = (const float*)d_in[3];
    const float* b_proj = (const float*)d_in[4];
    float* out = (float*)d_out;

    __nv_bfloat16 *qkvh, *qkvl, *xh, *xl, *wah, *wal, *wph, *wpl, *yh, *yl;
    cudaGetSymbolAddress((void**)&qkvh, g_qkvh);
    cudaGetSymbolAddress((void**)&qkvl, g_qkvl);
    cudaGetSymbolAddress((void**)&xh,  g_xh);
    cudaGetSymbolAddress((void**)&xl,  g_xl);
    cudaGetSymbolAddress((void**)&wah, g_wah);
    cudaGetSymbolAddress((void**)&wal, g_wal);
    cudaGetSymbolAddress((void**)&wph, g_wph);
    cudaGetSymbolAddress((void**)&wpl, g_wpl);
    cudaGetSymbolAddress((void**)&yh,  g_yh);
    cudaGetSymbolAddress((void**)&yl,  g_yl);

    cudaFuncSetAttribute(gemm_mma_bf16x3<0>,
                         cudaFuncAttributeMaxDynamicSharedMemorySize, GEMM_SMEM_BYTES);
    cudaFuncSetAttribute(gemm_mma_bf16x3<1>,
                         cudaFuncAttributeMaxDynamicSharedMemorySize, GEMM_SMEM_BYTES);
    cudaFuncSetAttribute(attn_mma,
                         cudaFuncAttributeMaxDynamicSharedMemorySize, ATTN_SMEM_BYTES);

    // 0) split inputs
    {
        int n4 = BT * EMBD / 4;
        split_bf16<<<(n4 + 255) / 256, 256>>>(x, xh, xl, n4);
        n4 = EMBD * C3 / 4;
        split_bf16<<<(n4 + 255) / 256, 256>>>(W_attn, wah, wal, n4);
        n4 = EMBD * EMBD / 4;
        split_bf16<<<(n4 + 255) / 256, 256>>>(W_proj, wph, wpl, n4);
    }
    // 1) QKV GEMM -> bf16 hi/lo qkv (bias fused, split fused)
    {
        dim3 grid(C3 / 128, BT / 128);
        gemm_mma_bf16x3<1><<<grid, 128, GEMM_SMEM_BYTES>>>(
            xh, xl, wah, wal, b_attn, nullptr, qkvh, qkvl, BT, C3, EMBD);
    }
    // 2) causal flash attention (mma.sync bf16x3) -> bf16 hi/lo y
    {
        dim3 grid(SEQ / 128, BATCH * NHEAD);
        attn_mma<<<grid, 256, ATTN_SMEM_BYTES>>>(qkvh, qkvl, yh, yl);
    }
    // 3) proj GEMM -> fp32 out
    {
        dim3 grid(EMBD / 128, BT / 128);
        gemm_mma_bf16x3<0><<<grid, 128, GEMM_SMEM_BYTES>>>(
            yh, yl, wph, wpl, b_proj, out, nullptr, nullptr, BT, EMBD, EMBD);
    }
}

// round 12
// speedup vs baseline: 2.8018x; 1.0018x over previous
#include <cuda_runtime.h>
#include <cuda_bf16.h>
#include <cstdint>

// ---------------------------------------------------------------------------
// Problem constants
// ---------------------------------------------------------------------------
#define BATCH 4
#define SEQ   2048
#define EMBD  1024
#define NHEAD 16
#define HDIM  64
#define BT    (BATCH*SEQ)        // 8192
#define C3    (3*EMBD)           // 3072

// ---------------------------------------------------------------------------
// Scratch (device globals — no allocation allowed)
// ---------------------------------------------------------------------------
__device__ __nv_bfloat16 g_qkvh[(size_t)BT * C3];
__device__ __nv_bfloat16 g_qkvl[(size_t)BT * C3];
__device__ __nv_bfloat16 g_xh[(size_t)BT * EMBD];
__device__ __nv_bfloat16 g_xl[(size_t)BT * EMBD];
__device__ __nv_bfloat16 g_wah[(size_t)EMBD * C3];
__device__ __nv_bfloat16 g_wal[(size_t)EMBD * C3];
__device__ __nv_bfloat16 g_wph[(size_t)EMBD * EMBD];
__device__ __nv_bfloat16 g_wpl[(size_t)EMBD * EMBD];
__device__ __nv_bfloat16 g_yh[(size_t)BT * EMBD];
__device__ __nv_bfloat16 g_yl[(size_t)BT * EMBD];

// ---------------------------------------------------------------------------
// PTX helpers (sm_80+ portable: mma.sync / ldmatrix / cp.async)
// ---------------------------------------------------------------------------
__device__ __forceinline__ uint32_t smem_to_u32(const void* smem_ptr) {
    uint32_t addr;
    asm("{ .reg .u64 tmp; cvta.to.shared.u64 tmp, %1; cvt.u32.u64 %0, tmp; }"
        : "=r"(addr) : "l"(smem_ptr));
    return addr;
}

#define CP_ASYNC16(saddr, gptr) \
    asm volatile("cp.async.cg.shared.global [%0], [%1], 16;" \
        :: "r"(saddr), "l"(gptr) : "memory")
#define CP_ASYNC_COMMIT() asm volatile("cp.async.commit_group;" ::: "memory")
#define CP_ASYNC_WAIT0()  asm volatile("cp.async.wait_group 0;" ::: "memory")
#define CP_ASYNC_WAIT1()  asm volatile("cp.async.wait_group 1;" ::: "memory")

#define LDMATRIX_X4(r0,r1,r2,r3, addr) \
    asm volatile("ldmatrix.sync.aligned.m8n8.x4.shared.b16 {%0,%1,%2,%3}, [%4];" \
        : "=r"(r0), "=r"(r1), "=r"(r2), "=r"(r3) : "r"(addr))

#define LDMATRIX_X4_T(r0,r1,r2,r3, addr) \
    asm volatile("ldmatrix.sync.aligned.m8n8.x4.trans.shared.b16 {%0,%1,%2,%3}, [%4];" \
        : "=r"(r0), "=r"(r1), "=r"(r2), "=r"(r3) : "r"(addr))

#define MMA_16816(d, a, b0v, b1v) \
    asm volatile( \
        "mma.sync.aligned.m16n8k16.row.col.f32.bf16.bf16.f32 " \
        "{%0,%1,%2,%3}, {%4,%5,%6,%7}, {%8,%9}, {%0,%1,%2,%3};" \
        : "+f"((d)[0]), "+f"((d)[1]), "+f"((d)[2]), "+f"((d)[3]) \
        : "r"((a)[0]), "r"((a)[1]), "r"((a)[2]), "r"((a)[3]), \
          "r"(b0v), "r"(b1v))

// split two fp32 into packed bf16x2 hi and lo
__device__ __forceinline__ void split2(float a, float b, uint32_t& h, uint32_t& l) {
    __nv_bfloat162 hh = __floats2bfloat162_rn(a, b);
    float2 hf = __bfloat1622float2(hh);
    __nv_bfloat162 ll = __floats2bfloat162_rn(a - hf.x, b - hf.y);
    h = *(uint32_t*)&hh;
    l = *(uint32_t*)&ll;
}

// ---------------------------------------------------------------------------
// Split fp32 -> (bf16 hi, bf16 lo)
// ---------------------------------------------------------------------------
__global__ __launch_bounds__(256) void split_bf16(
    const float* __restrict__ src,
    __nv_bfloat16* __restrict__ hi, __nv_bfloat16* __restrict__ lo, int n4)
{
    int i = blockIdx.x * 256 + threadIdx.x;
    if (i >= n4) return;
    float4 v = ((const float4*)src)[i];
    uint32_t h0, l0, h1, l1;
    split2(v.x, v.y, h0, l0);
    split2(v.z, v.w, h1, l1);
    ((uint32_t*)hi)[2*i]     = h0;
    ((uint32_t*)hi)[2*i + 1] = h1;
    ((uint32_t*)lo)[2*i]     = l0;
    ((uint32_t*)lo)[2*i + 1] = l1;
}

// ---------------------------------------------------------------------------
// mma.sync bf16x3 GEMM, 128x128 tile, 8 warps (warp tile 64x32),
// cp.async double buffer. Fragment double-buffering across the two k16
// phases: ALL ldmatrix for both phases are issued before the phase-0 MMA
// burst, so the LSU drains phase-1 fragments while the tensor pipe runs
// phase-0 — de-serializing the crossbar/tensor alternation.
// SPLIT_OUT=0: fp32 out (+bias). SPLIT_OUT=1: bf16 hi/lo out (+bias).
// ---------------------------------------------------------------------------
#define GOFF_AH 0u
#define GOFF_AL 10240u
#define GOFF_BH 20480u
#define GOFF_BL 29184u
#define GBUF    37888u
#define GEMM_SMEM_BYTES (2u * GBUF)

template<int SPLIT_OUT>
__global__ __launch_bounds__(256) void gemm_mma_bf16x3(
    const __nv_bfloat16* __restrict__ Ah, const __nv_bfloat16* __restrict__ Al,
    const __nv_bfloat16* __restrict__ Bh, const __nv_bfloat16* __restrict__ Bl,
    const float* __restrict__ bias, float* __restrict__ Cout,
    __nv_bfloat16* __restrict__ Ch, __nv_bfloat16* __restrict__ Cl,
    int M, int N, int K)
{
    extern __shared__ __align__(16) char smem[];
    const uint32_t sb = smem_to_u32(smem);
    const int tid  = threadIdx.x;
    const int warp = tid >> 5;
    const int lane = tid & 31;
    const int wm = warp & 1;
    const int wn = warp >> 1;
    const int row0 = blockIdx.y * 128;
    const int col0 = blockIdx.x * 128;

    const int ar = tid >> 2;
    const int ac = (tid & 3) * 8;
    const int bkr = tid >> 4;
    const int bnc = (tid & 15) * 8;

    const int nchunk = K >> 5;

    float acc[4][4][4];
    #pragma unroll
    for (int mt = 0; mt < 4; mt++)
        #pragma unroll
        for (int nt = 0; nt < 4; nt++)
            #pragma unroll
            for (int r = 0; r < 4; r++) acc[mt][nt][r] = 0.0f;

    {
        #pragma unroll
        for (int p = 0; p < 2; p++) {
            int r = ar + p * 64;
            CP_ASYNC16(sb + GOFF_AH + r*80 + ac*2, Ah + (size_t)(row0 + r) * K + ac);
            CP_ASYNC16(sb + GOFF_AL + r*80 + ac*2, Al + (size_t)(row0 + r) * K + ac);
            int kr = bkr + p * 16;
            CP_ASYNC16(sb + GOFF_BH + kr*272 + bnc*2, Bh + (size_t)kr * N + col0 + bnc);
            CP_ASYNC16(sb + GOFF_BL + kr*272 + bnc*2, Bl + (size_t)kr * N + col0 + bnc);
        }
        CP_ASYNC_COMMIT();
    }

    uint32_t buf = 0;
    for (int c = 0; c < nchunk; c++) {
        CP_ASYNC_WAIT0();
        __syncthreads();

        if (c + 1 < nchunk) {
            const uint32_t nb = sb + (buf ^ 1) * GBUF;
            const int kc0 = (c + 1) << 5;
            #pragma unroll
            for (int p = 0; p < 2; p++) {
                int r = ar + p * 64;
                CP_ASYNC16(nb + GOFF_AH + r*80 + ac*2, Ah + (size_t)(row0 + r) * K + kc0 + ac);
                CP_ASYNC16(nb + GOFF_AL + r*80 + ac*2, Al + (size_t)(row0 + r) * K + kc0 + ac);
                int kr = bkr + p * 16;
                CP_ASYNC16(nb + GOFF_BH + kr*272 + bnc*2, Bh + (size_t)(kc0 + kr) * N + col0 + bnc);
                CP_ASYNC16(nb + GOFF_BL + kr*272 + bnc*2, Bl + (size_t)(kc0 + kr) * N + col0 + bnc);
            }
            CP_ASYNC_COMMIT();
        }

        const uint32_t cb = sb + buf * GBUF;

        // ---- issue ALL fragment loads for both phases up front ----
        uint32_t a_h[2][4][4], a_l[2][4][4];   // [phase][mt][reg]
        uint32_t b_h[2][2][4], b_l[2][2][4];   // [phase][ntp][reg]
        const int g = lane >> 3;
        #pragma unroll
        for (int s = 0; s < 2; s++) {
            const int arow_base = wm * 64 + (lane & 15);
            const int acol = (s * 16 + (lane >> 4) * 8) * 2;
            #pragma unroll
            for (int mt = 0; mt < 4; mt++) {
                uint32_t off = (uint32_t)((arow_base + mt * 16) * 80 + acol);
                LDMATRIX_X4(a_h[s][mt][0], a_h[s][mt][1], a_h[s][mt][2], a_h[s][mt][3],
                            cb + GOFF_AH + off);
                LDMATRIX_X4(a_l[s][mt][0], a_l[s][mt][1], a_l[s][mt][2], a_l[s][mt][3],
                            cb + GOFF_AL + off);
            }
            const int krow = s * 16 + (g & 1) * 8 + (lane & 7);
            #pragma unroll
            for (int ntp = 0; ntp < 2; ntp++) {
                const int ncol = wn * 32 + ntp * 16 + (g >> 1) * 8;
                uint32_t off = (uint32_t)(krow * 272 + ncol * 2);
                LDMATRIX_X4_T(b_h[s][ntp][0], b_h[s][ntp][1], b_h[s][ntp][2], b_h[s][ntp][3],
                              cb + GOFF_BH + off);
                LDMATRIX_X4_T(b_l[s][ntp][0], b_l[s][ntp][1], b_l[s][ntp][2], b_l[s][ntp][3],
                              cb + GOFF_BL + off);
            }
        }

        // ---- MMA bursts; phase-1 LDS still draining during phase-0 MMAs ----
        #pragma unroll
        for (int s = 0; s < 2; s++) {
            #pragma unroll
            for (int combo = 0; combo < 3; combo++) {
                #pragma unroll
                for (int mt = 0; mt < 4; mt++) {
                    const uint32_t* av = (combo == 2) ? a_l[s][mt] : a_h[s][mt];
                    #pragma unroll
                    for (int nt = 0; nt < 4; nt++) {
                        const uint32_t b0v = (combo == 1) ? b_l[s][nt >> 1][(nt & 1) * 2]
                                                          : b_h[s][nt >> 1][(nt & 1) * 2];
                        const uint32_t b1v = (combo == 1) ? b_l[s][nt >> 1][(nt & 1) * 2 + 1]
                                                          : b_h[s][nt >> 1][(nt & 1) * 2 + 1];
                        MMA_16816(acc[mt][nt], av, b0v, b1v);
                    }
                }
            }
        }
        buf ^= 1;
    }

    const int er = (lane >> 2);
    const int ec = (lane & 3) * 2;
    #pragma unroll
    for (int mt = 0; mt < 4; mt++) {
        #pragma unroll
        for (int nt = 0; nt < 4; nt++) {
            const int r  = row0 + wm * 64 + mt * 16 + er;
            const int cc = col0 + wn * 32 + nt * 8 + ec;
            float2 bv = *(const float2*)(bias + cc);
            float o0x = acc[mt][nt][0] + bv.x;
            float o0y = acc[mt][nt][1] + bv.y;
            float o1x = acc[mt][nt][2] + bv.x;
            float o1y = acc[mt][nt][3] + bv.y;
            if (SPLIT_OUT) {
                uint32_t h0, l0, h1, l1;
                split2(o0x, o0y, h0, l0);
                split2(o1x, o1y, h1, l1);
                *(uint32_t*)(Ch + (size_t)r * N + cc)       = h0;
                *(uint32_t*)(Cl + (size_t)r * N + cc)       = l0;
                *(uint32_t*)(Ch + (size_t)(r + 8) * N + cc) = h1;
                *(uint32_t*)(Cl + (size_t)(r + 8) * N + cc) = l1;
            } else {
                *(float2*)(Cout + (size_t)r * N + cc)       = make_float2(o0x, o0y);
                *(float2*)(Cout + (size_t)(r + 8) * N + cc) = make_float2(o1x, o1y);
            }
        }
    }
}

// ---------------------------------------------------------------------------
// Flash attention (causal) with mma.sync bf16x3 — unchanged from R8 passing.
// ---------------------------------------------------------------------------
#define BKV 64
#define AROW 144              // bytes per smem row
#define OKH 0u
#define OKL 9216u
#define OVH 18432u
#define OVL 27648u
#define ABUF 36864u
#define ATTN_SMEM_BYTES (2u * ABUF)

__global__ __launch_bounds__(256) void attn_mma(
    const __nv_bfloat16* __restrict__ qkvh, const __nv_bfloat16* __restrict__ qkvl,
    __nv_bfloat16* __restrict__ Yh, __nv_bfloat16* __restrict__ Yl)
{
    extern __shared__ __align__(16) char smem[];
    const uint32_t sb = smem_to_u32(smem);
    const int tid  = threadIdx.x;
    const int warp = tid >> 5;
    const int lane = tid & 31;

    const int qt = (int)(gridDim.x - 1 - blockIdx.x);   // heavy tiles first
    const int bh = blockIdx.y;
    const int b  = bh >> 4;
    const int h  = bh & 15;

    const size_t rowbase = (size_t)b * SEQ * C3 + h * HDIM;
    const __nv_bfloat16* qh_g = qkvh + rowbase;
    const __nv_bfloat16* ql_g = qkvl + rowbase;
    const __nv_bfloat16* kh_g = qkvh + rowbase + EMBD;
    const __nv_bfloat16* kl_g = qkvl + rowbase + EMBD;
    const __nv_bfloat16* vh_g = qkvh + rowbase + 2 * EMBD;
    const __nv_bfloat16* vl_g = qkvl + rowbase + 2 * EMBD;

    // ---- stage Q (128 rows x 64) hi/lo into smem, then to registers ----
    {
        #pragma unroll
        for (int it = 0; it < 4; it++) {
            int i = tid + it * 256;
            int row = i >> 3, ch = i & 7;
            const size_t go = (size_t)(qt * 128 + row) * C3 + ch * 8;
            CP_ASYNC16(sb + row * AROW + ch * 16,         qh_g + go);
            CP_ASYNC16(sb + 18432 + row * AROW + ch * 16, ql_g + go);
        }
        CP_ASYNC_COMMIT();
        CP_ASYNC_WAIT0();
        __syncthreads();
    }

    uint32_t aqh[4][4], aql[4][4];
    {
        const int arow = warp * 16 + (lane & 15);
        const int acby = (lane >> 4) * 16;
        #pragma unroll
        for (int kt4 = 0; kt4 < 4; kt4++) {
            uint32_t off = (uint32_t)(arow * AROW + kt4 * 32 + acby);
            LDMATRIX_X4(aqh[kt4][0], aqh[kt4][1], aqh[kt4][2], aqh[kt4][3], sb + off);
            LDMATRIX_X4(aql[kt4][0], aql[kt4][1], aql[kt4][2], aql[kt4][3], sb + 18432 + off);
        }
    }
    __syncthreads();   // done reading Q smem before K/V overwrite

    // ---- softmax state + O accumulators ----
    float m0 = -1e30f, m1 = -1e30f, l0 = 0.0f, l1 = 0.0f;
    float o[8][4];
    #pragma unroll
    for (int nt = 0; nt < 8; nt++)
        #pragma unroll
        for (int r = 0; r < 4; r++) o[nt][r] = 0.0f;

    const int nkv = 2 * qt + 2;

    // prefetch KV tiles 0 and 1
    #pragma unroll
    for (int pf = 0; pf < 2; pf++) {
        if (pf < nkv) {
            const uint32_t dst = sb + pf * ABUF;
            #pragma unroll
            for (int it = 0; it < 2; it++) {
                int i = tid + it * 256;
                int row = i >> 3, ch = i & 7;
                const size_t go = (size_t)(pf * BKV + row) * C3 + ch * 8;
                const uint32_t so = row * AROW + ch * 16;
                CP_ASYNC16(dst + OKH + so, kh_g + go);
                CP_ASYNC16(dst + OKL + so, kl_g + go);
                CP_ASYNC16(dst + OVH + so, vh_g + go);
                CP_ASYNC16(dst + OVL + so, vl_g + go);
            }
            CP_ASYNC_COMMIT();
        }
    }

    const float scale = 0.125f;  // 1/sqrt(64)

    for (int kt = 0; kt < nkv; kt++) {
        if (kt + 1 < nkv) { CP_ASYNC_WAIT1(); } else { CP_ASYNC_WAIT0(); }
        __syncthreads();

        const uint32_t cb = sb + (kt & 1) * ABUF;

        // ---- S = Qh*Kh^T + Qh*Kl^T + Ql*Kh^T  (m16 x n64, k=64) ----
        float s[8][4];
        #pragma unroll
        for (int nt = 0; nt < 8; nt++)
            #pragma unroll
            for (int r = 0; r < 4; r++) s[nt][r] = 0.0f;

        const int g = lane >> 3;
        #pragma unroll
        for (int kt4 = 0; kt4 < 4; kt4++) {
            uint32_t bkh[4][4], bkl[4][4];
            #pragma unroll
            for (int nt16 = 0; nt16 < 4; nt16++) {
                const int nrow = nt16 * 16 + (g & 1) * 8 + (lane & 7);
                const uint32_t off = (uint32_t)(nrow * AROW + kt4 * 32 + (g >> 1) * 16);
                LDMATRIX_X4(bkh[nt16][0], bkh[nt16][1], bkh[nt16][2], bkh[nt16][3], cb + OKH + off);
                LDMATRIX_X4(bkl[nt16][0], bkl[nt16][1], bkl[nt16][2], bkl[nt16][3], cb + OKL + off);
            }
            // combo-outer: 8 independent MMAs between same-acc reuses
            #pragma unroll
            for (int combo = 0; combo < 3; combo++) {
                const uint32_t* aq = (combo == 2) ? aql[kt4] : aqh[kt4];
                #pragma unroll
                for (int nt16 = 0; nt16 < 4; nt16++) {
                    #pragma unroll
                    for (int hv = 0; hv < 2; hv++) {
                        const int nt8 = nt16 * 2 + hv;
                        const uint32_t b0v = (combo == 1) ? bkl[nt16][hv]     : bkh[nt16][hv];
                        const uint32_t b1v = (combo == 1) ? bkl[nt16][2 + hv] : bkh[nt16][2 + hv];
                        MMA_16816(s[nt8], aq, b0v, b1v);
                    }
                }
            }
        }

        // ---- online softmax ----
        const bool need_mask = (kt >= 2 * qt);
        const int r0g = qt * 128 + warp * 16 + (lane >> 2);
        const int r1g = r0g + 8;
        float rmax0 = -1e30f, rmax1 = -1e30f;
        #pragma unroll
        for (int nt = 0; nt < 8; nt++) {
            #pragma unroll
            for (int j = 0; j < 2; j++) {
                const int kc = kt * BKV + nt * 8 + (lane & 3) * 2 + j;
                float v0 = s[nt][j] * scale;
                float v1 = s[nt][2 + j] * scale;
                if (need_mask) {
                    if (kc > r0g) v0 = -1e30f;
                    if (kc > r1g) v1 = -1e30f;
                }
                s[nt][j] = v0;     rmax0 = fmaxf(rmax0, v0);
                s[nt][2 + j] = v1; rmax1 = fmaxf(rmax1, v1);
            }
        }
        rmax0 = fmaxf(rmax0, __shfl_xor_sync(0xffffffffu, rmax0, 1));
        rmax0 = fmaxf(rmax0, __shfl_xor_sync(0xffffffffu, rmax0, 2));
        rmax1 = fmaxf(rmax1, __shfl_xor_sync(0xffffffffu, rmax1, 1));
        rmax1 = fmaxf(rmax1, __shfl_xor_sync(0xffffffffu, rmax1, 2));

        const float mn0 = fmaxf(m0, rmax0);
        const float mn1 = fmaxf(m1, rmax1);
        const float alpha0 = __expf(m0 - mn0);
        const float alpha1 = __expf(m1 - mn1);
        m0 = mn0; m1 = mn1;

        float ps0 = 0.0f, ps1 = 0.0f;
        #pragma unroll
        for (int nt = 0; nt < 8; nt++) {
            #pragma unroll
            for (int j = 0; j < 2; j++) {
                float p0 = __expf(s[nt][j] - mn0);
                float p1 = __expf(s[nt][2 + j] - mn1);
                s[nt][j] = p0;     ps0 += p0;
                s[nt][2 + j] = p1; ps1 += p1;
            }
        }
        ps0 += __shfl_xor_sync(0xffffffffu, ps0, 1);
        ps0 += __shfl_xor_sync(0xffffffffu, ps0, 2);
        ps1 += __shfl_xor_sync(0xffffffffu, ps1, 1);
        ps1 += __shfl_xor_sync(0xffffffffu, ps1, 2);
        l0 = l0 * alpha0 + ps0;
        l1 = l1 * alpha1 + ps1;

        #pragma unroll
        for (int nt = 0; nt < 8; nt++) {
            o[nt][0] *= alpha0; o[nt][1] *= alpha0;
            o[nt][2] *= alpha1; o[nt][3] *= alpha1;
        }

        // ---- pack P -> bf16 hi/lo A-fragments (C-frag == A-frag mapping) ----
        uint32_t aph[4][4], apl[4][4];
        #pragma unroll
        for (int pt = 0; pt < 4; pt++) {
            split2(s[2*pt][0],   s[2*pt][1],   aph[pt][0], apl[pt][0]);
            split2(s[2*pt][2],   s[2*pt][3],   aph[pt][1], apl[pt][1]);
            split2(s[2*pt+1][0], s[2*pt+1][1], aph[pt][2], apl[pt][2]);
            split2(s[2*pt+1][2], s[2*pt+1][3], aph[pt][3], apl[pt][3]);
        }

        // ---- O += P @ V ----
        #pragma unroll
        for (int pt = 0; pt < 4; pt++) {
            uint32_t bvh[4][4], bvl[4][4];
            #pragma unroll
            for (int nt16 = 0; nt16 < 4; nt16++) {
                const int krow = pt * 16 + (g & 1) * 8 + (lane & 7);
                const uint32_t off = (uint32_t)(krow * AROW + nt16 * 32 + (g >> 1) * 16);
                LDMATRIX_X4_T(bvh[nt16][0], bvh[nt16][1], bvh[nt16][2], bvh[nt16][3], cb + OVH + off);
                LDMATRIX_X4_T(bvl[nt16][0], bvl[nt16][1], bvl[nt16][2], bvl[nt16][3], cb + OVL + off);
            }
            // combo-outer
            #pragma unroll
            for (int combo = 0; combo < 3; combo++) {
                const uint32_t* ap = (combo == 2) ? apl[pt] : aph[pt];
                #pragma unroll
                for (int nt16 = 0; nt16 < 4; nt16++) {
                    #pragma unroll
                    for (int hv = 0; hv < 2; hv++) {
                        const int nt8 = nt16 * 2 + hv;
                        const uint32_t b0v = (combo == 1) ? bvl[nt16][hv * 2]     : bvh[nt16][hv * 2];
                        const uint32_t b1v = (combo == 1) ? bvl[nt16][hv * 2 + 1] : bvh[nt16][hv * 2 + 1];
                        MMA_16816(o[nt8], ap, b0v, b1v);
                    }
                }
            }
        }

        __syncthreads();   // all warps done with this buffer

        if (kt + 2 < nkv) {
            const uint32_t dst = sb + (kt & 1) * ABUF;
            #pragma unroll
            for (int it = 0; it < 2; it++) {
                int i = tid + it * 256;
                int row = i >> 3, ch = i & 7;
                const size_t go = (size_t)((kt + 2) * BKV + row) * C3 + ch * 8;
                const uint32_t so = row * AROW + ch * 16;
                CP_ASYNC16(dst + OKH + so, kh_g + go);
                CP_ASYNC16(dst + OKL + so, kl_g + go);
                CP_ASYNC16(dst + OVH + so, vh_g + go);
                CP_ASYNC16(dst + OVL + so, vl_g + go);
            }
            CP_ASYNC_COMMIT();
        }
    }

    // ---- epilogue: normalize, split to bf16 hi/lo, store ----
    const float inv0 = 1.0f / l0;
    const float inv1 = 1.0f / l1;
    const int tr0 = qt * 128 + warp * 16 + (lane >> 2);
    const size_t ybase = (size_t)b * SEQ * EMBD + h * HDIM;
    #pragma unroll
    for (int nt = 0; nt < 8; nt++) {
        const int col = nt * 8 + (lane & 3) * 2;
        uint32_t h0, lo0, h1, lo1;
        split2(o[nt][0] * inv0, o[nt][1] * inv0, h0, lo0);
        split2(o[nt][2] * inv1, o[nt][3] * inv1, h1, lo1);
        *(uint32_t*)(Yh + ybase + (size_t)tr0 * EMBD + col)       = h0;
        *(uint32_t*)(Yl + ybase + (size_t)tr0 * EMBD + col)       = lo0;
        *(uint32_t*)(Yh + ybase + (size_t)(tr0 + 8) * EMBD + col) = h1;
        *(uint32_t*)(Yl + ybase + (size_t)(tr0 + 8) * EMBD + col) = lo1;
    }
}

// ---------------------------------------------------------------------------
extern "C" void kernel_launch(void* const* d_in, const int* in_sizes, int n_in,
                              void* d_out, int out_size)
{
    const float* x      = (const float*)d_in[0];
    const float* W_attn = (const float*)d_in[1];
    const float* b_attn = (const float*)d_in[2];
    const float* W_proj = (const float*)d_in[3];
    const float* b_proj = (const float*)d_in[4];
    float* out = (float*)d_out;

    __nv_bfloat16 *qkvh, *qkvl, *xh, *xl, *wah, *wal, *wph, *wpl, *yh, *yl;
    cudaGetSymbolAddress((void**)&qkvh, g_qkvh);
    cudaGetSymbolAddress((void**)&qkvl, g_qkvl);
    cudaGetSymbolAddress((void**)&xh,  g_xh);
    cudaGetSymbolAddress((void**)&xl,  g_xl);
    cudaGetSymbolAddress((void**)&wah, g_wah);
    cudaGetSymbolAddress((void**)&wal, g_wal);
    cudaGetSymbolAddress((void**)&wph, g_wph);
    cudaGetSymbolAddress((void**)&wpl, g_wpl);
    cudaGetSymbolAddress((void**)&yh,  g_yh);
    cudaGetSymbolAddress((void**)&yl,  g_yl);

    cudaFuncSetAttribute(gemm_mma_bf16x3<0>,
                         cudaFuncAttributeMaxDynamicSharedMemorySize, GEMM_SMEM_BYTES);
    cudaFuncSetAttribute(gemm_mma_bf16x3<1>,
                         cudaFuncAttributeMaxDynamicSharedMemorySize, GEMM_SMEM_BYTES);
    cudaFuncSetAttribute(attn_mma,
                         cudaFuncAttributeMaxDynamicSharedMemorySize, ATTN_SMEM_BYTES);

    // 0) split inputs
    {
        int n4 = BT * EMBD / 4;
        split_bf16<<<(n4 + 255) / 256, 256>>>(x, xh, xl, n4);
        n4 = EMBD * C3 / 4;
        split_bf16<<<(n4 + 255) / 256, 256>>>(W_attn, wah, wal, n4);
        n4 = EMBD * EMBD / 4;
        split_bf16<<<(n4 + 255) / 256, 256>>>(W_proj, wph, wpl, n4);
    }
    // 1) QKV GEMM -> bf16 hi/lo qkv (bias fused, split fused)
    {
        dim3 grid(C3 / 128, BT / 128);
        gemm_mma_bf16x3<1><<<grid, 256, GEMM_SMEM_BYTES>>>(
            xh, xl, wah, wal, b_attn, nullptr, qkvh, qkvl, BT, C3, EMBD);
    }
    // 2) causal flash attention (mma.sync bf16x3) -> bf16 hi/lo y
    {
        dim3 grid(SEQ / 128, BATCH * NHEAD);
        attn_mma<<<grid, 256, ATTN_SMEM_BYTES>>>(qkvh, qkvl, yh, yl);
    }
    // 3) proj GEMM -> fp32 out
    {
        dim3 grid(EMBD / 128, BT / 128);
        gemm_mma_bf16x3<0><<<grid, 256, GEMM_SMEM_BYTES>>>(
            yh, yl, wph, wpl, b_proj, out, nullptr, nullptr, BT, EMBD, EMBD);
    }
}